// round 3
// baseline (speedup 1.0000x reference)
#include <cuda_runtime.h>
#include <math.h>
#include <stdio.h>

// ---------------------------------------------------------------------------
// Problem constants
//  B=32, S=512, F_IN=64, D=512, DFF=2048, MEM=1024, L=3, H=8, dh=64
//  rows = B*S = 16384
// ---------------------------------------------------------------------------

// ------------------------- static scratch buffers --------------------------
__device__ float g_pe[512 * 512];            // 1 MB
__device__ float g_h[16384 * 512];           // 32 MB
__device__ float g_tmp[16384 * 512];         // 32 MB
__device__ float g_qkv[16384 * 1536];        // 96 MB
__device__ float g_scores[67108864];         // 256 MB  (32*8*512*512)
__device__ float g_o[16384 * 512];           // 32 MB
__device__ float g_ff[16384 * 2048];         // 128 MB
__device__ float g_upd[16384 * 512];         // 32 MB
__device__ float g_cat[16384 * 1024];        // 64 MB
__device__ float g_t1[16384 * 512];          // 32 MB
__device__ float g_fn[32 * 64];
__device__ float g_An[32 * 64 * 64];
__device__ float g_gt1[32 * 64 * 512];       // 4 MB
__device__ float g_gh1[32 * 64 * 512];       // 4 MB

// ---------------------------------------------------------------------------
// Positional encoding (match numpy float64 -> float32)
// ---------------------------------------------------------------------------
__global__ void pe_kernel(float* __restrict__ pe) {
    int i = blockIdx.x * 256 + threadIdx.x;
    if (i >= 512 * 512) return;
    int s = i >> 9, d = i & 511;
    int t2 = d & ~1;
    double div = exp((double)t2 * (-9.210340371976184 / 512.0)); // ln(10000)
    double a = (double)s * div;
    pe[i] = (float)((d & 1) ? cos(a) : sin(a));
}

// ---------------------------------------------------------------------------
// Generic SGEMM:  C[M,N] = A[M,K] * op(B) + bias (+relu / +pe)
//   TRANSB=true : B is (N,K) row-major  -> C = A @ B^T    (torch-style weight)
//   TRANSB=false: B is (K,N) row-major  -> C = A @ B
// M must be a multiple of 128. N,K arbitrary multiples of 4 (K mult of 16).
// EPI: 0 = bias, 1 = bias+relu, 2 = bias + positional encoding add
// ---------------------------------------------------------------------------
template <bool TRANSB, int EPI>
__global__ void __launch_bounds__(256) gemm_kernel(
    const float* __restrict__ A, const float* __restrict__ B,
    const float* __restrict__ bias, const float* __restrict__ pe,
    float* __restrict__ C, int M, int N, int K)
{
    __shared__ float As[16][132];
    __shared__ float Bs[16][132];
    const int tid = threadIdx.x;
    const int m0 = blockIdx.y * 128;
    const int n0 = blockIdx.x * 128;
    const int tx = tid & 15, ty = tid >> 4;
    const int lrow = tid >> 2;
    const int lcol = (tid & 3) << 2;

    float acc[8][8];
#pragma unroll
    for (int i = 0; i < 8; i++)
#pragma unroll
        for (int j = 0; j < 8; j++) acc[i][j] = 0.f;

    for (int k0 = 0; k0 < K; k0 += 16) {
#pragma unroll
        for (int hh = 0; hh < 2; hh++) {
            const int r = lrow + hh * 64;
            float4 v = *reinterpret_cast<const float4*>(
                A + (size_t)(m0 + r) * K + k0 + lcol);
            As[lcol + 0][r] = v.x; As[lcol + 1][r] = v.y;
            As[lcol + 2][r] = v.z; As[lcol + 3][r] = v.w;
        }
        if (TRANSB) {
#pragma unroll
            for (int hh = 0; hh < 2; hh++) {
                const int r = lrow + hh * 64;
                float4 v = make_float4(0.f, 0.f, 0.f, 0.f);
                if (n0 + r < N)
                    v = *reinterpret_cast<const float4*>(
                        B + (size_t)(n0 + r) * K + k0 + lcol);
                Bs[lcol + 0][r] = v.x; Bs[lcol + 1][r] = v.y;
                Bs[lcol + 2][r] = v.z; Bs[lcol + 3][r] = v.w;
            }
        } else {
            const int br = tid >> 5;
            const int bc = (tid & 31) << 2;
#pragma unroll
            for (int hh = 0; hh < 2; hh++) {
                const int r = br + hh * 8;
                float4 v = make_float4(0.f, 0.f, 0.f, 0.f);
                if (n0 + bc < N)
                    v = *reinterpret_cast<const float4*>(
                        B + (size_t)(k0 + r) * N + n0 + bc);
                *reinterpret_cast<float4*>(&Bs[r][bc]) = v;
            }
        }
        __syncthreads();
#pragma unroll
        for (int kk = 0; kk < 16; kk++) {
            float a[8], bb[8];
#pragma unroll
            for (int i = 0; i < 8; i++) a[i] = As[kk][ty + 16 * i];
#pragma unroll
            for (int j = 0; j < 8; j++) bb[j] = Bs[kk][tx + 16 * j];
#pragma unroll
            for (int i = 0; i < 8; i++)
#pragma unroll
                for (int j = 0; j < 8; j++)
                    acc[i][j] = fmaf(a[i], bb[j], acc[i][j]);
        }
        __syncthreads();
    }

#pragma unroll
    for (int i = 0; i < 8; i++) {
        const int m = m0 + ty + 16 * i;
#pragma unroll
        for (int j = 0; j < 8; j++) {
            const int n = n0 + tx + 16 * j;
            if (n < N) {
                float v = acc[i][j];
                if (bias) v += __ldg(bias + n);
                if (EPI == 1) v = fmaxf(v, 0.f);
                if (EPI == 2) v += pe[((m & 511) << 9) + n];
                C[(size_t)m * N + n] = v;
            }
        }
    }
}

// ---------------------------------------------------------------------------
// Attention scores: scores[bh, q, k] = (q . k) / 8
// qkv layout: [b, s, 1536] ; q at col h*64, k at 512+h*64, v at 1024+h*64
// grid (8 ktile, 8 qtile, 256 bh), block 256
// ---------------------------------------------------------------------------
__global__ void __launch_bounds__(256) attn_scores_kernel(
    const float* __restrict__ qkv, float* __restrict__ scores)
{
    const int kt = blockIdx.x, qt = blockIdx.y, bh = blockIdx.z;
    const int b = bh >> 3, h = bh & 7;
    __shared__ float Qs[64][65];
    __shared__ float Ks[64][65];
    const int tid = threadIdx.x;
    const int row = tid >> 2, seg = (tid & 3) << 4;

    const float* qbase = qkv + (size_t)(b * 512 + qt * 64 + row) * 1536 + h * 64 + seg;
    const float* kbase = qkv + (size_t)(b * 512 + kt * 64 + row) * 1536 + 512 + h * 64 + seg;
#pragma unroll
    for (int i = 0; i < 4; i++) {
        float4 v = *reinterpret_cast<const float4*>(qbase + i * 4);
        Qs[row][seg + i * 4 + 0] = v.x; Qs[row][seg + i * 4 + 1] = v.y;
        Qs[row][seg + i * 4 + 2] = v.z; Qs[row][seg + i * 4 + 3] = v.w;
        float4 w = *reinterpret_cast<const float4*>(kbase + i * 4);
        Ks[row][seg + i * 4 + 0] = w.x; Ks[row][seg + i * 4 + 1] = w.y;
        Ks[row][seg + i * 4 + 2] = w.z; Ks[row][seg + i * 4 + 3] = w.w;
    }
    __syncthreads();

    const int tx = tid & 15, ty = tid >> 4;
    float acc[4][4];
#pragma unroll
    for (int i = 0; i < 4; i++)
#pragma unroll
        for (int j = 0; j < 4; j++) acc[i][j] = 0.f;

#pragma unroll 8
    for (int d = 0; d < 64; d++) {
        float a[4], bb[4];
#pragma unroll
        for (int i = 0; i < 4; i++) a[i] = Qs[ty + 16 * i][d];
#pragma unroll
        for (int j = 0; j < 4; j++) bb[j] = Ks[tx + 16 * j][d];
#pragma unroll
        for (int i = 0; i < 4; i++)
#pragma unroll
            for (int j = 0; j < 4; j++)
                acc[i][j] = fmaf(a[i], bb[j], acc[i][j]);
    }

    float* out = scores + ((size_t)bh * 512 + qt * 64) * 512 + kt * 64;
#pragma unroll
    for (int i = 0; i < 4; i++)
#pragma unroll
        for (int j = 0; j < 4; j++)
            out[(size_t)(ty + 16 * i) * 512 + tx + 16 * j] = acc[i][j] * 0.125f;
}

// ---------------------------------------------------------------------------
// att @ v : o[b, q, h*64+d] = sum_k att[bh,q,k] * v[b,k,h*64+d]
// grid (8 qtile, 256 bh), block 256
// ---------------------------------------------------------------------------
__global__ void __launch_bounds__(256) attn_av_kernel(
    const float* __restrict__ scores, const float* __restrict__ qkv,
    float* __restrict__ o)
{
    const int qt = blockIdx.x, bh = blockIdx.y;
    const int b = bh >> 3, h = bh & 7;
    __shared__ float Ps[64][65];
    __shared__ float Vs[64][65];
    const int tid = threadIdx.x;
    const int row = tid >> 2, seg = (tid & 3) << 4;
    const int tx = tid & 15, ty = tid >> 4;

    float acc[4][4];
#pragma unroll
    for (int i = 0; i < 4; i++)
#pragma unroll
        for (int j = 0; j < 4; j++) acc[i][j] = 0.f;

    for (int kc = 0; kc < 8; kc++) {
        const float* pbase = scores + ((size_t)bh * 512 + qt * 64 + row) * 512 + kc * 64 + seg;
        const float* vbase = qkv + (size_t)(b * 512 + kc * 64 + row) * 1536 + 1024 + h * 64 + seg;
#pragma unroll
        for (int i = 0; i < 4; i++) {
            float4 v = *reinterpret_cast<const float4*>(pbase + i * 4);
            Ps[row][seg + i * 4 + 0] = v.x; Ps[row][seg + i * 4 + 1] = v.y;
            Ps[row][seg + i * 4 + 2] = v.z; Ps[row][seg + i * 4 + 3] = v.w;
            float4 w = *reinterpret_cast<const float4*>(vbase + i * 4);
            Vs[row][seg + i * 4 + 0] = w.x; Vs[row][seg + i * 4 + 1] = w.y;
            Vs[row][seg + i * 4 + 2] = w.z; Vs[row][seg + i * 4 + 3] = w.w;
        }
        __syncthreads();
#pragma unroll 8
        for (int kk = 0; kk < 64; kk++) {
            float a[4], bb[4];
#pragma unroll
            for (int i = 0; i < 4; i++) a[i] = Ps[ty + 16 * i][kk];
#pragma unroll
            for (int j = 0; j < 4; j++) bb[j] = Vs[kk][tx + 16 * j];
#pragma unroll
            for (int i = 0; i < 4; i++)
#pragma unroll
                for (int j = 0; j < 4; j++)
                    acc[i][j] = fmaf(a[i], bb[j], acc[i][j]);
        }
        __syncthreads();
    }

    float* ob = o + (size_t)(b * 512 + qt * 64) * 512 + h * 64;
#pragma unroll
    for (int i = 0; i < 4; i++)
#pragma unroll
        for (int j = 0; j < 4; j++)
            ob[(size_t)(ty + 16 * i) * 512 + tx + 16 * j] = acc[i][j];
}

// ---------------------------------------------------------------------------
// Row softmax, row length = CPT*256, one block of 256 threads per row
// ---------------------------------------------------------------------------
template <int CPT>
__global__ void __launch_bounds__(256) softmax_kernel(float* __restrict__ data)
{
    float* row = data + (size_t)blockIdx.x * (CPT * 256);
    const int tid = threadIdx.x;
    float x[CPT];
    float mx = -3.402823466e38f;
#pragma unroll
    for (int c = 0; c < CPT; c++) {
        x[c] = row[tid + 256 * c];
        mx = fmaxf(mx, x[c]);
    }
    __shared__ float sh[8];
#pragma unroll
    for (int o = 16; o; o >>= 1) mx = fmaxf(mx, __shfl_xor_sync(0xffffffffu, mx, o));
    if ((tid & 31) == 0) sh[tid >> 5] = mx;
    __syncthreads();
    mx = sh[0];
#pragma unroll
    for (int w = 1; w < 8; w++) mx = fmaxf(mx, sh[w]);

    float s = 0.f;
#pragma unroll
    for (int c = 0; c < CPT; c++) { x[c] = expf(x[c] - mx); s += x[c]; }
    __syncthreads();
#pragma unroll
    for (int o = 16; o; o >>= 1) s += __shfl_xor_sync(0xffffffffu, s, o);
    if ((tid & 31) == 0) sh[tid >> 5] = s;
    __syncthreads();
    float tot = sh[0];
#pragma unroll
    for (int w = 1; w < 8; w++) tot += sh[w];
    float inv = 1.f / tot;
#pragma unroll
    for (int c = 0; c < CPT; c++) row[tid + 256 * c] = x[c] * inv;
}

// ---------------------------------------------------------------------------
// out = LayerNorm(X + Y) * g + b  (row length 512, one block per row)
// ---------------------------------------------------------------------------
__global__ void __launch_bounds__(256) add_ln_kernel(
    const float* __restrict__ X, const float* __restrict__ Y,
    const float* __restrict__ gam, const float* __restrict__ bet,
    float* __restrict__ out)
{
    const size_t row = blockIdx.x;
    const float* xr = X + row * 512;
    const float* yr = Y + row * 512;
    const int tid = threadIdx.x;
    float t0 = xr[tid] + yr[tid];
    float t1 = xr[tid + 256] + yr[tid + 256];

    __shared__ float sh[8];
    float s = t0 + t1;
#pragma unroll
    for (int o = 16; o; o >>= 1) s += __shfl_xor_sync(0xffffffffu, s, o);
    if ((tid & 31) == 0) sh[tid >> 5] = s;
    __syncthreads();
    float tot = sh[0];
#pragma unroll
    for (int w = 1; w < 8; w++) tot += sh[w];
    float mean = tot * (1.f / 512.f);
    float d0 = t0 - mean, d1 = t1 - mean;
    float q = d0 * d0 + d1 * d1;
    __syncthreads();
#pragma unroll
    for (int o = 16; o; o >>= 1) q += __shfl_xor_sync(0xffffffffu, q, o);
    if ((tid & 31) == 0) sh[tid >> 5] = q;
    __syncthreads();
    float vtot = sh[0];
#pragma unroll
    for (int w = 1; w < 8; w++) vtot += sh[w];
    float inv = rsqrtf(vtot * (1.f / 512.f) + 1e-5f);
    float* orow = out + row * 512;
    orow[tid] = d0 * inv * gam[tid] + bet[tid];
    orow[tid + 256] = d1 * inv * gam[tid + 256] + bet[tid + 256];
}

// ---------------------------------------------------------------------------
// cat = [h | upd]  (16384 x 1024)
// ---------------------------------------------------------------------------
__global__ void concat_kernel(const float* __restrict__ a,
                              const float* __restrict__ b,
                              float* __restrict__ c)
{
    size_t i = (size_t)blockIdx.x * 256 + threadIdx.x;
    if (i >= (size_t)16384 * 128) return; // float4 count per half
    size_t r = i >> 7, col = i & 127;
    const float4* a4 = reinterpret_cast<const float4*>(a);
    const float4* b4 = reinterpret_cast<const float4*>(b);
    float4* c4 = reinterpret_cast<float4*>(c);
    c4[r * 256 + col] = a4[i];
    c4[r * 256 + 128 + col] = b4[i];
}

// ---------------------------------------------------------------------------
// Graph branch
// ---------------------------------------------------------------------------
__global__ void feat_fn_kernel(const float* __restrict__ x, float* __restrict__ fn)
{
    const int b = blockIdx.x, i = threadIdx.x; // 64 threads
    const float* xp = x + (size_t)b * 32768 + i;
    float s = 0.f;
    for (int t = 0; t < 512; t++) s += xp[(size_t)t * 64];
    float f = s * (1.f / 512.f);
    __shared__ float sh[64];
    sh[i] = f * f;
    __syncthreads();
    for (int o = 32; o; o >>= 1) {
        if (i < o) sh[i] += sh[i + o];
        __syncthreads();
    }
    float norm = sqrtf(sh[0]);
    fn[b * 64 + i] = f / fmaxf(norm, 1e-12f);
}

__global__ void graph_adj_kernel(const float* __restrict__ fn, float* __restrict__ An)
{
    const int b = blockIdx.x, i = threadIdx.x; // 64 threads
    __shared__ float f[64];
    __shared__ unsigned char A[64][64];
    f[i] = fn[b * 64 + i];
    for (int j = 0; j < 64; j++) A[i][j] = 0;
    __syncthreads();
    const float fi = f[i];
    float bv0 = -3.402823466e38f, bv1 = bv0, bv2 = bv0, bv3 = bv0;
    int i0 = 0, i1 = 0, i2 = 0, i3 = 0;
    for (int j = 0; j < 64; j++) {
        float v = fi * f[j];
        if (v > bv3) {
            if (v > bv0)      { bv3 = bv2; i3 = i2; bv2 = bv1; i2 = i1; bv1 = bv0; i1 = i0; bv0 = v; i0 = j; }
            else if (v > bv1) { bv3 = bv2; i3 = i2; bv2 = bv1; i2 = i1; bv1 = v; i1 = j; }
            else if (v > bv2) { bv3 = bv2; i3 = i2; bv2 = v; i2 = j; }
            else              { bv3 = v; i3 = j; }
        }
    }
    A[i][i1] = 1; A[i][i2] = 1; A[i][i3] = 1;
    __syncthreads();
    float deg = 0.f;
    for (int j = 0; j < 64; j++) {
        bool a = (j == i) || A[i][j] || A[j][i];
        deg += a ? 1.f : 0.f;
    }
    float inv = 1.f / deg;
    float* row = An + (size_t)b * 4096 + i * 64;
    for (int j = 0; j < 64; j++) {
        bool a = (j == i) || A[i][j] || A[j][i];
        row[j] = a ? inv : 0.f;
    }
}

// t1[b,f,d] = sum_s x[b,s,f] * w[d,s] + bias[d]   (M=64 f, N=512 d, K=512 s)
__global__ void __launch_bounds__(256) gcn_gemm1_kernel(
    const float* __restrict__ x, const float* __restrict__ w,
    const float* __restrict__ bias, float* __restrict__ out)
{
    const int dt = blockIdx.x, b = blockIdx.y;
    __shared__ float Xs[16][64];
    __shared__ float Ws[64][17];
    const int tid = threadIdx.x, tx = tid & 15, ty = tid >> 4;
    float acc[4][4];
#pragma unroll
    for (int i = 0; i < 4; i++)
#pragma unroll
        for (int j = 0; j < 4; j++) acc[i][j] = 0.f;

    for (int k0 = 0; k0 < 512; k0 += 16) {
        {
            int kk = tid >> 4, f4 = (tid & 15) << 2;
            float4 v = *reinterpret_cast<const float4*>(
                x + (size_t)b * 32768 + (size_t)(k0 + kk) * 64 + f4);
            *reinterpret_cast<float4*>(&Xs[kk][f4]) = v;
            int dd = tid >> 2, k4 = (tid & 3) << 2;
            float4 w4 = *reinterpret_cast<const float4*>(
                w + (size_t)(dt * 64 + dd) * 512 + k0 + k4);
            Ws[dd][k4 + 0] = w4.x; Ws[dd][k4 + 1] = w4.y;
            Ws[dd][k4 + 2] = w4.z; Ws[dd][k4 + 3] = w4.w;
        }
        __syncthreads();
#pragma unroll
        for (int kk = 0; kk < 16; kk++) {
            float a[4], bb[4];
#pragma unroll
            for (int i = 0; i < 4; i++) a[i] = Xs[kk][ty + 16 * i];
#pragma unroll
            for (int j = 0; j < 4; j++) bb[j] = Ws[tx + 16 * j][kk];
#pragma unroll
            for (int i = 0; i < 4; i++)
#pragma unroll
                for (int j = 0; j < 4; j++)
                    acc[i][j] = fmaf(a[i], bb[j], acc[i][j]);
        }
        __syncthreads();
    }
#pragma unroll
    for (int i = 0; i < 4; i++)
#pragma unroll
        for (int j = 0; j < 4; j++) {
            int dd = dt * 64 + tx + 16 * j;
            out[(size_t)b * 32768 + (size_t)(ty + 16 * i) * 512 + dd] =
                acc[i][j] + bias[dd];
        }
}

// t2[b,f,s] = sum_d Ain[b,f,d] * w[s,d] + bias[s]
__global__ void __launch_bounds__(256) gcn_gemm2_kernel(
    const float* __restrict__ Ain, const float* __restrict__ w,
    const float* __restrict__ bias, float* __restrict__ out)
{
    const int st = blockIdx.x, b = blockIdx.y;
    __shared__ float As[64][17];
    __shared__ float Ws[64][17];
    const int tid = threadIdx.x, tx = tid & 15, ty = tid >> 4;
    const int rr = tid >> 2, k4 = (tid & 3) << 2;
    float acc[4][4];
#pragma unroll
    for (int i = 0; i < 4; i++)
#pragma unroll
        for (int j = 0; j < 4; j++) acc[i][j] = 0.f;

    for (int k0 = 0; k0 < 512; k0 += 16) {
        float4 a4 = *reinterpret_cast<const float4*>(
            Ain + (size_t)b * 32768 + (size_t)rr * 512 + k0 + k4);
        As[rr][k4 + 0] = a4.x; As[rr][k4 + 1] = a4.y;
        As[rr][k4 + 2] = a4.z; As[rr][k4 + 3] = a4.w;
        float4 w4 = *reinterpret_cast<const float4*>(
            w + (size_t)(st * 64 + rr) * 512 + k0 + k4);
        Ws[rr][k4 + 0] = w4.x; Ws[rr][k4 + 1] = w4.y;
        Ws[rr][k4 + 2] = w4.z; Ws[rr][k4 + 3] = w4.w;
        __syncthreads();
#pragma unroll
        for (int kk = 0; kk < 16; kk++) {
            float a[4], bb[4];
#pragma unroll
            for (int i = 0; i < 4; i++) a[i] = As[ty + 16 * i][kk];
#pragma unroll
            for (int j = 0; j < 4; j++) bb[j] = Ws[tx + 16 * j][kk];
#pragma unroll
            for (int i = 0; i < 4; i++)
#pragma unroll
                for (int j = 0; j < 4; j++)
                    acc[i][j] = fmaf(a[i], bb[j], acc[i][j]);
        }
        __syncthreads();
    }
#pragma unroll
    for (int i = 0; i < 4; i++)
#pragma unroll
        for (int j = 0; j < 4; j++) {
            int ss = st * 64 + tx + 16 * j;
            out[(size_t)b * 32768 + (size_t)(ty + 16 * i) * 512 + ss] =
                acc[i][j] + bias[ss];
        }
}

// out = (relu?) An @ in ; optional transposed write g_out[b, s, f]
// grid (8 dtile, 32 b)
template <bool RELU, bool TRANSOUT>
__global__ void __launch_bounds__(256) an_mult_kernel(
    const float* __restrict__ An, const float* __restrict__ in,
    float* __restrict__ out)
{
    const int dt = blockIdx.x, b = blockIdx.y;
    __shared__ float As[64][65];
    __shared__ float Ins[64][64];
    const int tid = threadIdx.x, tx = tid & 15, ty = tid >> 4;

    for (int t = tid; t < 4096; t += 256)
        As[t >> 6][t & 63] = An[(size_t)b * 4096 + t];
#pragma unroll
    for (int hh = 0; hh < 4; hh++) {
        int idx4 = tid + hh * 256;
        int gg = idx4 >> 4, c4 = (idx4 & 15) << 2;
        float4 v = *reinterpret_cast<const float4*>(
            in + (size_t)b * 32768 + (size_t)gg * 512 + dt * 64 + c4);
        *reinterpret_cast<float4*>(&Ins[gg][c4]) = v;
    }
    __syncthreads();

    float acc[4][4];
#pragma unroll
    for (int i = 0; i < 4; i++)
#pragma unroll
        for (int j = 0; j < 4; j++) acc[i][j] = 0.f;

#pragma unroll 8
    for (int kk = 0; kk < 64; kk++) {
        float a[4], bb[4];
#pragma unroll
        for (int i = 0; i < 4; i++) a[i] = As[ty + 16 * i][kk];
#pragma unroll
        for (int j = 0; j < 4; j++) bb[j] = Ins[kk][tx + 16 * j];
#pragma unroll
        for (int i = 0; i < 4; i++)
#pragma unroll
            for (int j = 0; j < 4; j++)
                acc[i][j] = fmaf(a[i], bb[j], acc[i][j]);
    }

#pragma unroll
    for (int i = 0; i < 4; i++)
#pragma unroll
        for (int j = 0; j < 4; j++) {
            int ff = ty + 16 * i;
            int dd = dt * 64 + tx + 16 * j;
            float v = acc[i][j];
            if (RELU) v = fmaxf(v, 0.f);
            if (!TRANSOUT)
                out[(size_t)b * 32768 + (size_t)ff * 512 + dd] = v;
            else
                out[(size_t)b * 32768 + (size_t)dd * 64 + ff] = v;
        }
}

// ---------------------------------------------------------------------------
// Host orchestration
// ---------------------------------------------------------------------------
extern "C" void kernel_launch(void* const* d_in, const int* in_sizes, int n_in,
                              void* d_out, int out_size)
{
    const float* x      = (const float*)d_in[0];
    const float* W_in   = (const float*)d_in[1];
    const float* b_in   = (const float*)d_in[2];
    const float* qkv_w  = (const float*)d_in[3];
    const float* qkv_b  = (const float*)d_in[4];
    const float* out_w  = (const float*)d_in[5];
    const float* out_b  = (const float*)d_in[6];
    const float* ln1_g  = (const float*)d_in[7];
    const float* ln1_b  = (const float*)d_in[8];
    const float* ln2_g  = (const float*)d_in[9];
    const float* ln2_b  = (const float*)d_in[10];
    const float* ff1_w  = (const float*)d_in[11];
    const float* ff1_b  = (const float*)d_in[12];
    const float* ff2_w  = (const float*)d_in[13];
    const float* ff2_b  = (const float*)d_in[14];
    const float* memory = (const float*)d_in[15];
    const float* fc1_w  = (const float*)d_in[16];
    const float* fc1_b  = (const float*)d_in[17];
    const float* fc2_w  = (const float*)d_in[18];
    const float* fc2_b  = (const float*)d_in[19];
    const float* gc1_w  = (const float*)d_in[20];
    const float* gc1_b  = (const float*)d_in[21];
    const float* gc2_w  = (const float*)d_in[22];
    const float* gc2_b  = (const float*)d_in[23];

    float* out    = (float*)d_out;
    float* t_out  = out;                       // (32,512,64)
    float* gout_p = out + 1048576;             // (32,512,64)
    float* attn_p = out + 2097152;             // (32,512,1024)

    static float *p_pe = nullptr, *p_h, *p_tmp, *p_qkv, *p_sc, *p_o, *p_ff,
                 *p_upd, *p_cat, *p_t1, *p_fn, *p_An, *p_gt1, *p_gh1;
    if (!p_pe) {
        cudaGetSymbolAddress((void**)&p_pe,  g_pe);
        cudaGetSymbolAddress((void**)&p_h,   g_h);
        cudaGetSymbolAddress((void**)&p_tmp, g_tmp);
        cudaGetSymbolAddress((void**)&p_qkv, g_qkv);
        cudaGetSymbolAddress((void**)&p_sc,  g_scores);
        cudaGetSymbolAddress((void**)&p_o,   g_o);
        cudaGetSymbolAddress((void**)&p_ff,  g_ff);
        cudaGetSymbolAddress((void**)&p_upd, g_upd);
        cudaGetSymbolAddress((void**)&p_cat, g_cat);
        cudaGetSymbolAddress((void**)&p_t1,  g_t1);
        cudaGetSymbolAddress((void**)&p_fn,  g_fn);
        cudaGetSymbolAddress((void**)&p_An,  g_An);
        cudaGetSymbolAddress((void**)&p_gt1, g_gt1);
        cudaGetSymbolAddress((void**)&p_gh1, g_gh1);
    }

    const int M = 16384;

    // positional encoding
    pe_kernel<<<(512 * 512 + 255) / 256, 256>>>(p_pe);

    // h = x @ W_in^T + b_in + pe
    gemm_kernel<true, 2><<<dim3(4, 128), 256>>>(x, W_in, b_in, p_pe, p_h, M, 512, 64);

    for (int l = 0; l < 3; l++) {
        // qkv
        gemm_kernel<true, 0><<<dim3(12, 128), 256>>>(
            p_h, qkv_w + (size_t)l * 1536 * 512, qkv_b + l * 1536, nullptr,
            p_qkv, M, 1536, 512);
        // scores + softmax + att@v
        attn_scores_kernel<<<dim3(8, 8, 256), 256>>>(p_qkv, p_sc);
        softmax_kernel<2><<<131072, 256>>>(p_sc);
        attn_av_kernel<<<dim3(8, 256), 256>>>(p_sc, p_qkv, p_o);
        // out projection
        gemm_kernel<true, 0><<<dim3(4, 128), 256>>>(
            p_o, out_w + (size_t)l * 512 * 512, out_b + l * 512, nullptr,
            p_tmp, M, 512, 512);
        add_ln_kernel<<<16384, 256>>>(p_h, p_tmp, ln1_g + l * 512, ln1_b + l * 512, p_h);
        // feed-forward
        gemm_kernel<true, 1><<<dim3(16, 128), 256>>>(
            p_h, ff1_w + (size_t)l * 2048 * 512, ff1_b + l * 2048, nullptr,
            p_ff, M, 2048, 512);
        gemm_kernel<true, 0><<<dim3(4, 128), 256>>>(
            p_ff, ff2_w + (size_t)l * 512 * 2048, ff2_b + l * 512, nullptr,
            p_tmp, M, 512, 2048);
        add_ln_kernel<<<16384, 256>>>(p_h, p_tmp, ln2_g + l * 512, ln2_b + l * 512, p_h);
    }

    // memory attention: sims -> softmax -> upd
    gemm_kernel<true, 0><<<dim3(8, 128), 256>>>(p_h, memory, nullptr, nullptr,
                                                attn_p, M, 1024, 512);
    softmax_kernel<4><<<16384, 256>>>(attn_p);
    gemm_kernel<false, 0><<<dim3(4, 128), 256>>>(attn_p, memory, nullptr, nullptr,
                                                 p_upd, M, 512, 1024);
    // concat + fc1(relu) + fc2
    concat_kernel<<<(16384 * 128 + 255) / 256, 256>>>(p_h, p_upd, p_cat);
    gemm_kernel<true, 1><<<dim3(4, 128), 256>>>(p_cat, fc1_w, fc1_b, nullptr,
                                                p_t1, M, 512, 1024);
    gemm_kernel<true, 0><<<dim3(1, 128), 256>>>(p_t1, fc2_w, fc2_b, nullptr,
                                                t_out, M, 64, 512);

    // graph branch
    feat_fn_kernel<<<32, 64>>>(x, p_fn);
    graph_adj_kernel<<<32, 64>>>(p_fn, p_An);
    gcn_gemm1_kernel<<<dim3(8, 32), 256>>>(x, gc1_w, gc1_b, p_gt1);
    an_mult_kernel<true, false><<<dim3(8, 32), 256>>>(p_An, p_gt1, p_gh1);
    gcn_gemm2_kernel<<<dim3(8, 32), 256>>>(p_gh1, gc2_w, gc2_b, p_gt1);
    an_mult_kernel<false, true><<<dim3(8, 32), 256>>>(p_An, p_gt1, gout_p);

    (void)in_sizes; (void)n_in; (void)out_size;
}

// round 4
// speedup vs baseline: 2.4669x; 2.4669x over previous
#include <cuda_runtime.h>
#include <math.h>
#include <stdint.h>

// ---------------------------------------------------------------------------
// Problem constants
//  B=32, S=512, F_IN=64, D=512, DFF=2048, MEM=1024, L=3, H=8, dh=64
//  rows = B*S = 16384
// ---------------------------------------------------------------------------

// ------------------------- static scratch buffers --------------------------
__device__ float g_pe[512 * 512];            // 1 MB
__device__ float g_h[16384 * 512];           // 32 MB
__device__ float g_tmp[16384 * 512];         // 32 MB
__device__ float g_qkv[16384 * 1536];        // 96 MB
__device__ float g_scores[67108864];         // 256 MB  (32*8*512*512)
__device__ float g_o[16384 * 512];           // 32 MB
__device__ float g_ff[16384 * 2048];         // 128 MB
__device__ float g_upd[16384 * 512];         // 32 MB
__device__ float g_cat[16384 * 1024];        // 64 MB
__device__ float g_t1[16384 * 512];          // 32 MB
__device__ float g_fn[32 * 64];
__device__ float g_An[32 * 64 * 64];
__device__ float g_gt1[32 * 64 * 512];       // 4 MB
__device__ float g_gh1[32 * 64 * 512];       // 4 MB

// ---------------------------------------------------------------------------
// tf32 helpers
// ---------------------------------------------------------------------------
__device__ __forceinline__ float tf32_rna(float x) {
    uint32_t u;
    asm("cvt.rna.tf32.f32 %0, %1;" : "=r"(u) : "f"(x));
    return __uint_as_float(u);
}

__device__ __forceinline__ void mma_tf32(float c[4],
    uint32_t a0, uint32_t a1, uint32_t a2, uint32_t a3,
    uint32_t b0, uint32_t b1)
{
    asm volatile(
        "mma.sync.aligned.m16n8k8.row.col.f32.tf32.tf32.f32 "
        "{%0,%1,%2,%3}, {%4,%5,%6,%7}, {%8,%9}, {%0,%1,%2,%3};"
        : "+f"(c[0]), "+f"(c[1]), "+f"(c[2]), "+f"(c[3])
        : "r"(a0), "r"(a1), "r"(a2), "r"(a3), "r"(b0), "r"(b1));
}

// ---------------------------------------------------------------------------
// Positional encoding (match numpy float64 -> float32)
// ---------------------------------------------------------------------------
__global__ void pe_kernel(float* __restrict__ pe) {
    int i = blockIdx.x * 256 + threadIdx.x;
    if (i >= 512 * 512) return;
    int s = i >> 9, d = i & 511;
    int t2 = d & ~1;
    double div = exp((double)t2 * (-9.210340371976184 / 512.0)); // ln(10000)
    double a = (double)s * div;
    pe[i] = (float)((d & 1) ? cos(a) : sin(a));
}

// ---------------------------------------------------------------------------
// Tensor-core GEMM: C[M,N] = A[M,K] * op(B) + bias (+relu / +pe)
//   TRANSB=true : B is (N,K) row-major  -> C = A @ B^T
//   TRANSB=false: B is (K,N) row-major  -> C = A @ B
//   SPLIT=true  : 3xTF32 (hi/lo split) for ~fp32 accuracy
// Block tile 128x128, 256 threads (8 warps = 2m x 4n of 64x32 warp tiles).
// M multiple of 128; K multiple of KT; N arbitrary multiple of 4.
// EPI: 0 = bias, 1 = bias+relu, 2 = bias + positional encoding add
// ---------------------------------------------------------------------------
template <bool TRANSB, int EPI, bool SPLIT>
__global__ void __launch_bounds__(256) gemm_tc(
    const float* __restrict__ A, const float* __restrict__ B,
    const float* __restrict__ bias, const float* __restrict__ pe,
    float* __restrict__ C, int M, int N, int K)
{
    constexpr int KT   = SPLIT ? 16 : 32;
    constexpr int STR  = KT + 4;           // stride ≡ 4 (mod 32): conflict-free frags
    constexpr int TILE = 128 * STR;
    constexpr int KG   = KT / 4;           // float4 per row
    constexpr int ITS  = KT / 8;           // loader iterations (128*KG/256)

    __shared__ float As[(SPLIT ? 2 : 1) * TILE];
    __shared__ float Bs[(SPLIT ? 2 : 1) * TILE];

    const int tid  = threadIdx.x;
    const int lane = tid & 31, wid = tid >> 5;
    const int wm = (wid >> 2) * 64, wn = (wid & 3) * 32;
    const int r = lane >> 2, c = lane & 3;
    const int m0 = blockIdx.y * 128, n0 = blockIdx.x * 128;

    float acc[4][4][4];
#pragma unroll
    for (int i = 0; i < 4; i++)
#pragma unroll
        for (int j = 0; j < 4; j++)
#pragma unroll
            for (int t = 0; t < 4; t++) acc[i][j][t] = 0.f;

    for (int k0 = 0; k0 < K; k0 += KT) {
        // ---- load A tile (m-rows, k-cols), coalesced, tf32-converted ----
#pragma unroll
        for (int i = 0; i < ITS; i++) {
            int idx = tid + i * 256;
            int kg = idx & (KG - 1), m = idx / KG;
            float4 v = *reinterpret_cast<const float4*>(
                A + (size_t)(m0 + m) * K + k0 + kg * 4);
            float4 h;
            h.x = tf32_rna(v.x); h.y = tf32_rna(v.y);
            h.z = tf32_rna(v.z); h.w = tf32_rna(v.w);
            *reinterpret_cast<float4*>(&As[m * STR + kg * 4]) = h;
            if (SPLIT) {
                float4 l;
                l.x = tf32_rna(v.x - h.x); l.y = tf32_rna(v.y - h.y);
                l.z = tf32_rna(v.z - h.z); l.w = tf32_rna(v.w - h.w);
                *reinterpret_cast<float4*>(&As[TILE + m * STR + kg * 4]) = l;
            }
        }
        // ---- load B tile into Bs[n][k] ----
        if (TRANSB) {
#pragma unroll
            for (int i = 0; i < ITS; i++) {
                int idx = tid + i * 256;
                int kg = idx & (KG - 1), n = idx / KG;
                float4 v = make_float4(0.f, 0.f, 0.f, 0.f);
                if (n0 + n < N)
                    v = *reinterpret_cast<const float4*>(
                        B + (size_t)(n0 + n) * K + k0 + kg * 4);
                float4 h;
                h.x = tf32_rna(v.x); h.y = tf32_rna(v.y);
                h.z = tf32_rna(v.z); h.w = tf32_rna(v.w);
                *reinterpret_cast<float4*>(&Bs[n * STR + kg * 4]) = h;
                if (SPLIT) {
                    float4 l;
                    l.x = tf32_rna(v.x - h.x); l.y = tf32_rna(v.y - h.y);
                    l.z = tf32_rna(v.z - h.z); l.w = tf32_rna(v.w - h.w);
                    *reinterpret_cast<float4*>(&Bs[TILE + n * STR + kg * 4]) = l;
                }
            }
        } else {
#pragma unroll
            for (int i = 0; i < ITS; i++) {
                int idx = tid + i * 256;
                int ng = idx & 31, kk = idx >> 5;   // kk < KT
                int n = ng * 4;
                float4 v = make_float4(0.f, 0.f, 0.f, 0.f);
                if (n0 + n < N)
                    v = *reinterpret_cast<const float4*>(
                        B + (size_t)(k0 + kk) * N + n0 + n);
                float h0 = tf32_rna(v.x), h1 = tf32_rna(v.y);
                float h2 = tf32_rna(v.z), h3 = tf32_rna(v.w);
                Bs[(n + 0) * STR + kk] = h0; Bs[(n + 1) * STR + kk] = h1;
                Bs[(n + 2) * STR + kk] = h2; Bs[(n + 3) * STR + kk] = h3;
                if (SPLIT) {
                    Bs[TILE + (n + 0) * STR + kk] = tf32_rna(v.x - h0);
                    Bs[TILE + (n + 1) * STR + kk] = tf32_rna(v.y - h1);
                    Bs[TILE + (n + 2) * STR + kk] = tf32_rna(v.z - h2);
                    Bs[TILE + (n + 3) * STR + kk] = tf32_rna(v.w - h3);
                }
            }
        }
        __syncthreads();

#pragma unroll
        for (int ks = 0; ks < KT / 8; ks++) {
            const int kb = ks * 8 + c;
            uint32_t af[4][4], bf[4][2];
#pragma unroll
            for (int mi = 0; mi < 4; mi++) {
                const int mr = wm + mi * 16 + r;
                af[mi][0] = __float_as_uint(As[mr * STR + kb]);
                af[mi][1] = __float_as_uint(As[(mr + 8) * STR + kb]);
                af[mi][2] = __float_as_uint(As[mr * STR + kb + 4]);
                af[mi][3] = __float_as_uint(As[(mr + 8) * STR + kb + 4]);
            }
#pragma unroll
            for (int ni = 0; ni < 4; ni++) {
                const int nr = wn + ni * 8 + r;
                bf[ni][0] = __float_as_uint(Bs[nr * STR + kb]);
                bf[ni][1] = __float_as_uint(Bs[nr * STR + kb + 4]);
            }
#pragma unroll
            for (int mi = 0; mi < 4; mi++)
#pragma unroll
                for (int ni = 0; ni < 4; ni++)
                    mma_tf32(acc[mi][ni], af[mi][0], af[mi][1], af[mi][2], af[mi][3],
                             bf[ni][0], bf[ni][1]);
            if (SPLIT) {
                uint32_t afl[4][4], bfl[4][2];
#pragma unroll
                for (int mi = 0; mi < 4; mi++) {
                    const int mr = wm + mi * 16 + r;
                    afl[mi][0] = __float_as_uint(As[TILE + mr * STR + kb]);
                    afl[mi][1] = __float_as_uint(As[TILE + (mr + 8) * STR + kb]);
                    afl[mi][2] = __float_as_uint(As[TILE + mr * STR + kb + 4]);
                    afl[mi][3] = __float_as_uint(As[TILE + (mr + 8) * STR + kb + 4]);
                }
#pragma unroll
                for (int ni = 0; ni < 4; ni++) {
                    const int nr = wn + ni * 8 + r;
                    bfl[ni][0] = __float_as_uint(Bs[TILE + nr * STR + kb]);
                    bfl[ni][1] = __float_as_uint(Bs[TILE + nr * STR + kb + 4]);
                }
#pragma unroll
                for (int mi = 0; mi < 4; mi++)
#pragma unroll
                    for (int ni = 0; ni < 4; ni++) {
                        mma_tf32(acc[mi][ni], af[mi][0], af[mi][1], af[mi][2], af[mi][3],
                                 bfl[ni][0], bfl[ni][1]);
                        mma_tf32(acc[mi][ni], afl[mi][0], afl[mi][1], afl[mi][2], afl[mi][3],
                                 bf[ni][0], bf[ni][1]);
                    }
            }
        }
        __syncthreads();
    }

    // ---- epilogue ----
#pragma unroll
    for (int mi = 0; mi < 4; mi++) {
#pragma unroll
        for (int ni = 0; ni < 4; ni++) {
            const int row = m0 + wm + mi * 16 + r;
            const int col = n0 + wn + ni * 8 + 2 * c;
#pragma unroll
            for (int t = 0; t < 4; t++) {
                const int rr2 = row + (t >= 2 ? 8 : 0);
                const int cc2 = col + (t & 1);
                if (cc2 < N) {
                    float v = acc[mi][ni][t];
                    if (bias) v += __ldg(bias + cc2);
                    if (EPI == 1) v = fmaxf(v, 0.f);
                    if (EPI == 2) v += pe[((rr2 & 511) << 9) + cc2];
                    C[(size_t)rr2 * N + cc2] = v;
                }
            }
        }
    }
}

// ---------------------------------------------------------------------------
// Attention scores (tensor core): scores[bh,q,k] = (q.k)/8
// grid (8 ktile, 8 qtile, 256 bh), 128 threads (4 warps, 32x32 warp tiles)
// ---------------------------------------------------------------------------
__global__ void __launch_bounds__(128) attn_scores_tc(
    const float* __restrict__ qkv, float* __restrict__ scores)
{
    const int kt = blockIdx.x, qt = blockIdx.y, bh = blockIdx.z;
    const int b = bh >> 3, h = bh & 7;
    constexpr int STR = 68;                  // 64 + 4
    __shared__ float Qs[64 * STR];
    __shared__ float Ks[64 * STR];
    const int tid = threadIdx.x, lane = tid & 31, wid = tid >> 5;
    const int wm = (wid >> 1) * 32, wn = (wid & 1) * 32;
    const int r = lane >> 2, c = lane & 3;

#pragma unroll
    for (int i = 0; i < 8; i++) {
        int idx = tid + i * 128;
        int kg = idx & 15, m = idx >> 4;
        float4 v = *reinterpret_cast<const float4*>(
            qkv + (size_t)(b * 512 + qt * 64 + m) * 1536 + h * 64 + kg * 4);
        float4 hq;
        hq.x = tf32_rna(v.x); hq.y = tf32_rna(v.y);
        hq.z = tf32_rna(v.z); hq.w = tf32_rna(v.w);
        *reinterpret_cast<float4*>(&Qs[m * STR + kg * 4]) = hq;
        float4 w = *reinterpret_cast<const float4*>(
            qkv + (size_t)(b * 512 + kt * 64 + m) * 1536 + 512 + h * 64 + kg * 4);
        float4 hk;
        hk.x = tf32_rna(w.x); hk.y = tf32_rna(w.y);
        hk.z = tf32_rna(w.z); hk.w = tf32_rna(w.w);
        *reinterpret_cast<float4*>(&Ks[m * STR + kg * 4]) = hk;
    }
    __syncthreads();

    float acc[2][4][4];
#pragma unroll
    for (int i = 0; i < 2; i++)
#pragma unroll
        for (int j = 0; j < 4; j++)
#pragma unroll
            for (int t = 0; t < 4; t++) acc[i][j][t] = 0.f;

#pragma unroll
    for (int ks = 0; ks < 8; ks++) {
        const int kb = ks * 8 + c;
        uint32_t af[2][4], bf[4][2];
#pragma unroll
        for (int mi = 0; mi < 2; mi++) {
            const int mr = wm + mi * 16 + r;
            af[mi][0] = __float_as_uint(Qs[mr * STR + kb]);
            af[mi][1] = __float_as_uint(Qs[(mr + 8) * STR + kb]);
            af[mi][2] = __float_as_uint(Qs[mr * STR + kb + 4]);
            af[mi][3] = __float_as_uint(Qs[(mr + 8) * STR + kb + 4]);
        }
#pragma unroll
        for (int ni = 0; ni < 4; ni++) {
            const int nr = wn + ni * 8 + r;
            bf[ni][0] = __float_as_uint(Ks[nr * STR + kb]);
            bf[ni][1] = __float_as_uint(Ks[nr * STR + kb + 4]);
        }
#pragma unroll
        for (int mi = 0; mi < 2; mi++)
#pragma unroll
            for (int ni = 0; ni < 4; ni++)
                mma_tf32(acc[mi][ni], af[mi][0], af[mi][1], af[mi][2], af[mi][3],
                         bf[ni][0], bf[ni][1]);
    }

#pragma unroll
    for (int mi = 0; mi < 2; mi++)
#pragma unroll
        for (int ni = 0; ni < 4; ni++) {
            const int row = qt * 64 + wm + mi * 16 + r;
            const int col = kt * 64 + wn + ni * 8 + 2 * c;
            float* o = scores + ((size_t)bh * 512 + row) * 512 + col;
            o[0]            = acc[mi][ni][0] * 0.125f;
            o[1]            = acc[mi][ni][1] * 0.125f;
            o[8 * 512]      = acc[mi][ni][2] * 0.125f;
            o[8 * 512 + 1]  = acc[mi][ni][3] * 0.125f;
        }
}

// ---------------------------------------------------------------------------
// att @ v (tensor core): o[b,q,h*64+d] = sum_k att[bh,q,k] * v[b,k,h*64+d]
// grid (8 qtile, 256 bh), 128 threads
// ---------------------------------------------------------------------------
__global__ void __launch_bounds__(128) attn_av_tc(
    const float* __restrict__ scores, const float* __restrict__ qkv,
    float* __restrict__ o)
{
    const int qt = blockIdx.x, bh = blockIdx.y;
    const int b = bh >> 3, h = bh & 7;
    constexpr int STR = 68;
    __shared__ float Ps[64 * STR];
    __shared__ float Vs[64 * STR];
    const int tid = threadIdx.x, lane = tid & 31, wid = tid >> 5;
    const int wm = (wid >> 1) * 32, wn = (wid & 1) * 32;
    const int r = lane >> 2, c = lane & 3;

    float acc[2][4][4];
#pragma unroll
    for (int i = 0; i < 2; i++)
#pragma unroll
        for (int j = 0; j < 4; j++)
#pragma unroll
            for (int t = 0; t < 4; t++) acc[i][j][t] = 0.f;

    for (int kc = 0; kc < 8; kc++) {
#pragma unroll
        for (int i = 0; i < 8; i++) {
            int idx = tid + i * 128;
            {   // P: att rows (q, k) -> Ps[m][k], direct copy
                int kg = idx & 15, m = idx >> 4;
                float4 v = *reinterpret_cast<const float4*>(
                    scores + ((size_t)bh * 512 + qt * 64 + m) * 512 + kc * 64 + kg * 4);
                float4 hp;
                hp.x = tf32_rna(v.x); hp.y = tf32_rna(v.y);
                hp.z = tf32_rna(v.z); hp.w = tf32_rna(v.w);
                *reinterpret_cast<float4*>(&Ps[m * STR + kg * 4]) = hp;
            }
            {   // V: (k, d) -> Vs[d][k], transposed scatter
                int dg = idx & 15, k = idx >> 4;
                float4 v = *reinterpret_cast<const float4*>(
                    qkv + (size_t)(b * 512 + kc * 64 + k) * 1536 + 1024 + h * 64 + dg * 4);
                Vs[(dg * 4 + 0) * STR + k] = tf32_rna(v.x);
                Vs[(dg * 4 + 1) * STR + k] = tf32_rna(v.y);
                Vs[(dg * 4 + 2) * STR + k] = tf32_rna(v.z);
                Vs[(dg * 4 + 3) * STR + k] = tf32_rna(v.w);
            }
        }
        __syncthreads();

#pragma unroll
        for (int ks = 0; ks < 8; ks++) {
            const int kb = ks * 8 + c;
            uint32_t af[2][4], bf[4][2];
#pragma unroll
            for (int mi = 0; mi < 2; mi++) {
                const int mr = wm + mi * 16 + r;
                af[mi][0] = __float_as_uint(Ps[mr * STR + kb]);
                af[mi][1] = __float_as_uint(Ps[(mr + 8) * STR + kb]);
                af[mi][2] = __float_as_uint(Ps[mr * STR + kb + 4]);
                af[mi][3] = __float_as_uint(Ps[(mr + 8) * STR + kb + 4]);
            }
#pragma unroll
            for (int ni = 0; ni < 4; ni++) {
                const int nr = wn + ni * 8 + r;
                bf[ni][0] = __float_as_uint(Vs[nr * STR + kb]);
                bf[ni][1] = __float_as_uint(Vs[nr * STR + kb + 4]);
            }
#pragma unroll
            for (int mi = 0; mi < 2; mi++)
#pragma unroll
                for (int ni = 0; ni < 4; ni++)
                    mma_tf32(acc[mi][ni], af[mi][0], af[mi][1], af[mi][2], af[mi][3],
                             bf[ni][0], bf[ni][1]);
        }
        __syncthreads();
    }

#pragma unroll
    for (int mi = 0; mi < 2; mi++)
#pragma unroll
        for (int ni = 0; ni < 4; ni++) {
            const int row = qt * 64 + wm + mi * 16 + r;
            const int col = wn + ni * 8 + 2 * c;
            float* ob = o + (size_t)(b * 512 + row) * 512 + h * 64 + col;
            ob[0]           = acc[mi][ni][0];
            ob[1]           = acc[mi][ni][1];
            ob[8 * 512]     = acc[mi][ni][2];
            ob[8 * 512 + 1] = acc[mi][ni][3];
        }
}

// ---------------------------------------------------------------------------
// Row softmax, row length = CPT*256, one block of 256 threads per row
// ---------------------------------------------------------------------------
template <int CPT>
__global__ void __launch_bounds__(256) softmax_kernel(float* __restrict__ data)
{
    float* row = data + (size_t)blockIdx.x * (CPT * 256);
    const int tid = threadIdx.x;
    float x[CPT];
    float mx = -3.402823466e38f;
#pragma unroll
    for (int c = 0; c < CPT; c++) {
        x[c] = row[tid + 256 * c];
        mx = fmaxf(mx, x[c]);
    }
    __shared__ float sh[8];
#pragma unroll
    for (int o = 16; o; o >>= 1) mx = fmaxf(mx, __shfl_xor_sync(0xffffffffu, mx, o));
    if ((tid & 31) == 0) sh[tid >> 5] = mx;
    __syncthreads();
    mx = sh[0];
#pragma unroll
    for (int w = 1; w < 8; w++) mx = fmaxf(mx, sh[w]);

    float s = 0.f;
#pragma unroll
    for (int c = 0; c < CPT; c++) { x[c] = expf(x[c] - mx); s += x[c]; }
    __syncthreads();
#pragma unroll
    for (int o = 16; o; o >>= 1) s += __shfl_xor_sync(0xffffffffu, s, o);
    if ((tid & 31) == 0) sh[tid >> 5] = s;
    __syncthreads();
    float tot = sh[0];
#pragma unroll
    for (int w = 1; w < 8; w++) tot += sh[w];
    float inv = 1.f / tot;
#pragma unroll
    for (int c = 0; c < CPT; c++) row[tid + 256 * c] = x[c] * inv;
}

// ---------------------------------------------------------------------------
// out = LayerNorm(X + Y) * g + b  (row length 512, one block per row)
// ---------------------------------------------------------------------------
__global__ void __launch_bounds__(256) add_ln_kernel(
    const float* __restrict__ X, const float* __restrict__ Y,
    const float* __restrict__ gam, const float* __restrict__ bet,
    float* __restrict__ out)
{
    const size_t row = blockIdx.x;
    const float* xr = X + row * 512;
    const float* yr = Y + row * 512;
    const int tid = threadIdx.x;
    float t0 = xr[tid] + yr[tid];
    float t1 = xr[tid + 256] + yr[tid + 256];

    __shared__ float sh[8];
    float s = t0 + t1;
#pragma unroll
    for (int o = 16; o; o >>= 1) s += __shfl_xor_sync(0xffffffffu, s, o);
    if ((tid & 31) == 0) sh[tid >> 5] = s;
    __syncthreads();
    float tot = sh[0];
#pragma unroll
    for (int w = 1; w < 8; w++) tot += sh[w];
    float mean = tot * (1.f / 512.f);
    float d0 = t0 - mean, d1 = t1 - mean;
    float q = d0 * d0 + d1 * d1;
    __syncthreads();
#pragma unroll
    for (int o = 16; o; o >>= 1) q += __shfl_xor_sync(0xffffffffu, q, o);
    if ((tid & 31) == 0) sh[tid >> 5] = q;
    __syncthreads();
    float vtot = sh[0];
#pragma unroll
    for (int w = 1; w < 8; w++) vtot += sh[w];
    float inv = rsqrtf(vtot * (1.f / 512.f) + 1e-5f);
    float* orow = out + row * 512;
    orow[tid] = d0 * inv * gam[tid] + bet[tid];
    orow[tid + 256] = d1 * inv * gam[tid + 256] + bet[tid + 256];
}

// ---------------------------------------------------------------------------
// cat = [h | upd]  (16384 x 1024)
// ---------------------------------------------------------------------------
__global__ void concat_kernel(const float* __restrict__ a,
                              const float* __restrict__ b,
                              float* __restrict__ c)
{
    size_t i = (size_t)blockIdx.x * 256 + threadIdx.x;
    if (i >= (size_t)16384 * 128) return; // float4 count per half
    size_t r = i >> 7, col = i & 127;
    const float4* a4 = reinterpret_cast<const float4*>(a);
    const float4* b4 = reinterpret_cast<const float4*>(b);
    float4* c4 = reinterpret_cast<float4*>(c);
    c4[r * 256 + col] = a4[i];
    c4[r * 256 + 128 + col] = b4[i];
}

// ---------------------------------------------------------------------------
// Graph branch (exact fp32, tiny cost)
// ---------------------------------------------------------------------------
__global__ void feat_fn_kernel(const float* __restrict__ x, float* __restrict__ fn)
{
    const int b = blockIdx.x, i = threadIdx.x; // 64 threads
    const float* xp = x + (size_t)b * 32768 + i;
    float s = 0.f;
    for (int t = 0; t < 512; t++) s += xp[(size_t)t * 64];
    float f = s * (1.f / 512.f);
    __shared__ float sh[64];
    sh[i] = f * f;
    __syncthreads();
    for (int o = 32; o; o >>= 1) {
        if (i < o) sh[i] += sh[i + o];
        __syncthreads();
    }
    float norm = sqrtf(sh[0]);
    fn[b * 64 + i] = f / fmaxf(norm, 1e-12f);
}

__global__ void graph_adj_kernel(const float* __restrict__ fn, float* __restrict__ An)
{
    const int b = blockIdx.x, i = threadIdx.x; // 64 threads
    __shared__ float f[64];
    __shared__ unsigned char A[64][64];
    f[i] = fn[b * 64 + i];
    for (int j = 0; j < 64; j++) A[i][j] = 0;
    __syncthreads();
    const float fi = f[i];
    float bv0 = -3.402823466e38f, bv1 = bv0, bv2 = bv0, bv3 = bv0;
    int i0 = 0, i1 = 0, i2 = 0, i3 = 0;
    for (int j = 0; j < 64; j++) {
        float v = fi * f[j];
        if (v > bv3) {
            if (v > bv0)      { bv3 = bv2; i3 = i2; bv2 = bv1; i2 = i1; bv1 = bv0; i1 = i0; bv0 = v; i0 = j; }
            else if (v > bv1) { bv3 = bv2; i3 = i2; bv2 = bv1; i2 = i1; bv1 = v; i1 = j; }
            else if (v > bv2) { bv3 = bv2; i3 = i2; bv2 = v; i2 = j; }
            else              { bv3 = v; i3 = j; }
        }
    }
    A[i][i1] = 1; A[i][i2] = 1; A[i][i3] = 1;
    __syncthreads();
    float deg = 0.f;
    for (int j = 0; j < 64; j++) {
        bool a = (j == i) || A[i][j] || A[j][i];
        deg += a ? 1.f : 0.f;
    }
    float inv = 1.f / deg;
    float* row = An + (size_t)b * 4096 + i * 64;
    for (int j = 0; j < 64; j++) {
        bool a = (j == i) || A[i][j] || A[j][i];
        row[j] = a ? inv : 0.f;
    }
}

// t1[b,f,d] = sum_s x[b,s,f] * w[d,s] + bias[d]   (M=64 f, N=512 d, K=512 s)
__global__ void __launch_bounds__(256) gcn_gemm1_kernel(
    const float* __restrict__ x, const float* __restrict__ w,
    const float* __restrict__ bias, float* __restrict__ out)
{
    const int dt = blockIdx.x, b = blockIdx.y;
    __shared__ float Xs[16][64];
    __shared__ float Ws[64][17];
    const int tid = threadIdx.x, tx = tid & 15, ty = tid >> 4;
    float acc[4][4];
#pragma unroll
    for (int i = 0; i < 4; i++)
#pragma unroll
        for (int j = 0; j < 4; j++) acc[i][j] = 0.f;

    for (int k0 = 0; k0 < 512; k0 += 16) {
        {
            int kk = tid >> 4, f4 = (tid & 15) << 2;
            float4 v = *reinterpret_cast<const float4*>(
                x + (size_t)b * 32768 + (size_t)(k0 + kk) * 64 + f4);
            *reinterpret_cast<float4*>(&Xs[kk][f4]) = v;
            int dd = tid >> 2, k4 = (tid & 3) << 2;
            float4 w4 = *reinterpret_cast<const float4*>(
                w + (size_t)(dt * 64 + dd) * 512 + k0 + k4);
            Ws[dd][k4 + 0] = w4.x; Ws[dd][k4 + 1] = w4.y;
            Ws[dd][k4 + 2] = w4.z; Ws[dd][k4 + 3] = w4.w;
        }
        __syncthreads();
#pragma unroll
        for (int kk = 0; kk < 16; kk++) {
            float a[4], bb[4];
#pragma unroll
            for (int i = 0; i < 4; i++) a[i] = Xs[kk][ty + 16 * i];
#pragma unroll
            for (int j = 0; j < 4; j++) bb[j] = Ws[tx + 16 * j][kk];
#pragma unroll
            for (int i = 0; i < 4; i++)
#pragma unroll
                for (int j = 0; j < 4; j++)
                    acc[i][j] = fmaf(a[i], bb[j], acc[i][j]);
        }
        __syncthreads();
    }
#pragma unroll
    for (int i = 0; i < 4; i++)
#pragma unroll
        for (int j = 0; j < 4; j++) {
            int dd = dt * 64 + tx + 16 * j;
            out[(size_t)b * 32768 + (size_t)(ty + 16 * i) * 512 + dd] =
                acc[i][j] + bias[dd];
        }
}

// t2[b,f,s] = sum_d Ain[b,f,d] * w[s,d] + bias[s]
__global__ void __launch_bounds__(256) gcn_gemm2_kernel(
    const float* __restrict__ Ain, const float* __restrict__ w,
    const float* __restrict__ bias, float* __restrict__ out)
{
    const int st = blockIdx.x, b = blockIdx.y;
    __shared__ float As[64][17];
    __shared__ float Ws[64][17];
    const int tid = threadIdx.x, tx = tid & 15, ty = tid >> 4;
    const int rr = tid >> 2, k4 = (tid & 3) << 2;
    float acc[4][4];
#pragma unroll
    for (int i = 0; i < 4; i++)
#pragma unroll
        for (int j = 0; j < 4; j++) acc[i][j] = 0.f;

    for (int k0 = 0; k0 < 512; k0 += 16) {
        float4 a4 = *reinterpret_cast<const float4*>(
            Ain + (size_t)b * 32768 + (size_t)rr * 512 + k0 + k4);
        As[rr][k4 + 0] = a4.x; As[rr][k4 + 1] = a4.y;
        As[rr][k4 + 2] = a4.z; As[rr][k4 + 3] = a4.w;
        float4 w4 = *reinterpret_cast<const float4*>(
            w + (size_t)(st * 64 + rr) * 512 + k0 + k4);
        Ws[rr][k4 + 0] = w4.x; Ws[rr][k4 + 1] = w4.y;
        Ws[rr][k4 + 2] = w4.z; Ws[rr][k4 + 3] = w4.w;
        __syncthreads();
#pragma unroll
        for (int kk = 0; kk < 16; kk++) {
            float a[4], bb[4];
#pragma unroll
            for (int i = 0; i < 4; i++) a[i] = As[ty + 16 * i][kk];
#pragma unroll
            for (int j = 0; j < 4; j++) bb[j] = Ws[tx + 16 * j][kk];
#pragma unroll
            for (int i = 0; i < 4; i++)
#pragma unroll
                for (int j = 0; j < 4; j++)
                    acc[i][j] = fmaf(a[i], bb[j], acc[i][j]);
        }
        __syncthreads();
    }
#pragma unroll
    for (int i = 0; i < 4; i++)
#pragma unroll
        for (int j = 0; j < 4; j++) {
            int ss = st * 64 + tx + 16 * j;
            out[(size_t)b * 32768 + (size_t)(ty + 16 * i) * 512 + ss] =
                acc[i][j] + bias[ss];
        }
}

// out = (relu?) An @ in ; optional transposed write g_out[b, s, f]
template <bool RELU, bool TRANSOUT>
__global__ void __launch_bounds__(256) an_mult_kernel(
    const float* __restrict__ An, const float* __restrict__ in,
    float* __restrict__ out)
{
    const int dt = blockIdx.x, b = blockIdx.y;
    __shared__ float As[64][65];
    __shared__ float Ins[64][64];
    const int tid = threadIdx.x, tx = tid & 15, ty = tid >> 4;

    for (int t = tid; t < 4096; t += 256)
        As[t >> 6][t & 63] = An[(size_t)b * 4096 + t];
#pragma unroll
    for (int hh = 0; hh < 4; hh++) {
        int idx4 = tid + hh * 256;
        int gg = idx4 >> 4, c4 = (idx4 & 15) << 2;
        float4 v = *reinterpret_cast<const float4*>(
            in + (size_t)b * 32768 + (size_t)gg * 512 + dt * 64 + c4);
        *reinterpret_cast<float4*>(&Ins[gg][c4]) = v;
    }
    __syncthreads();

    float acc[4][4];
#pragma unroll
    for (int i = 0; i < 4; i++)
#pragma unroll
        for (int j = 0; j < 4; j++) acc[i][j] = 0.f;

#pragma unroll 8
    for (int kk = 0; kk < 64; kk++) {
        float a[4], bb[4];
#pragma unroll
        for (int i = 0; i < 4; i++) a[i] = As[ty + 16 * i][kk];
#pragma unroll
        for (int j = 0; j < 4; j++) bb[j] = Ins[kk][tx + 16 * j];
#pragma unroll
        for (int i = 0; i < 4; i++)
#pragma unroll
            for (int j = 0; j < 4; j++)
                acc[i][j] = fmaf(a[i], bb[j], acc[i][j]);
    }

#pragma unroll
    for (int i = 0; i < 4; i++)
#pragma unroll
        for (int j = 0; j < 4; j++) {
            int ff = ty + 16 * i;
            int dd = dt * 64 + tx + 16 * j;
            float v = acc[i][j];
            if (RELU) v = fmaxf(v, 0.f);
            if (!TRANSOUT)
                out[(size_t)b * 32768 + (size_t)ff * 512 + dd] = v;
            else
                out[(size_t)b * 32768 + (size_t)dd * 64 + ff] = v;
        }
}

// ---------------------------------------------------------------------------
// Host orchestration
// ---------------------------------------------------------------------------
extern "C" void kernel_launch(void* const* d_in, const int* in_sizes, int n_in,
                              void* d_out, int out_size)
{
    const float* x      = (const float*)d_in[0];
    const float* W_in   = (const float*)d_in[1];
    const float* b_in   = (const float*)d_in[2];
    const float* qkv_w  = (const float*)d_in[3];
    const float* qkv_b  = (const float*)d_in[4];
    const float* out_w  = (const float*)d_in[5];
    const float* out_b  = (const float*)d_in[6];
    const float* ln1_g  = (const float*)d_in[7];
    const float* ln1_b  = (const float*)d_in[8];
    const float* ln2_g  = (const float*)d_in[9];
    const float* ln2_b  = (const float*)d_in[10];
    const float* ff1_w  = (const float*)d_in[11];
    const float* ff1_b  = (const float*)d_in[12];
    const float* ff2_w  = (const float*)d_in[13];
    const float* ff2_b  = (const float*)d_in[14];
    const float* memory = (const float*)d_in[15];
    const float* fc1_w  = (const float*)d_in[16];
    const float* fc1_b  = (const float*)d_in[17];
    const float* fc2_w  = (const float*)d_in[18];
    const float* fc2_b  = (const float*)d_in[19];
    const float* gc1_w  = (const float*)d_in[20];
    const float* gc1_b  = (const float*)d_in[21];
    const float* gc2_w  = (const float*)d_in[22];
    const float* gc2_b  = (const float*)d_in[23];

    float* out    = (float*)d_out;
    float* t_out  = out;                       // (32,512,64)
    float* gout_p = out + 1048576;             // (32,512,64)
    float* attn_p = out + 2097152;             // (32,512,1024)

    static float *p_pe = nullptr, *p_h, *p_tmp, *p_qkv, *p_sc, *p_o, *p_ff,
                 *p_upd, *p_cat, *p_t1, *p_fn, *p_An, *p_gt1, *p_gh1;
    if (!p_pe) {
        cudaGetSymbolAddress((void**)&p_pe,  g_pe);
        cudaGetSymbolAddress((void**)&p_h,   g_h);
        cudaGetSymbolAddress((void**)&p_tmp, g_tmp);
        cudaGetSymbolAddress((void**)&p_qkv, g_qkv);
        cudaGetSymbolAddress((void**)&p_sc,  g_scores);
        cudaGetSymbolAddress((void**)&p_o,   g_o);
        cudaGetSymbolAddress((void**)&p_ff,  g_ff);
        cudaGetSymbolAddress((void**)&p_upd, g_upd);
        cudaGetSymbolAddress((void**)&p_cat, g_cat);
        cudaGetSymbolAddress((void**)&p_t1,  g_t1);
        cudaGetSymbolAddress((void**)&p_fn,  g_fn);
        cudaGetSymbolAddress((void**)&p_An,  g_An);
        cudaGetSymbolAddress((void**)&p_gt1, g_gt1);
        cudaGetSymbolAddress((void**)&p_gh1, g_gh1);
    }

    const int M = 16384;

    // positional encoding
    pe_kernel<<<(512 * 512 + 255) / 256, 256>>>(p_pe);

    // h = x @ W_in^T + b_in + pe
    gemm_tc<true, 2, false><<<dim3(4, 128), 256>>>(x, W_in, b_in, p_pe, p_h, M, 512, 64);

    for (int l = 0; l < 3; l++) {
        // qkv
        gemm_tc<true, 0, false><<<dim3(12, 128), 256>>>(
            p_h, qkv_w + (size_t)l * 1536 * 512, qkv_b + l * 1536, nullptr,
            p_qkv, M, 1536, 512);
        // scores + softmax + att@v
        attn_scores_tc<<<dim3(8, 8, 256), 128>>>(p_qkv, p_sc);
        softmax_kernel<2><<<131072, 256>>>(p_sc);
        attn_av_tc<<<dim3(8, 256), 128>>>(p_sc, p_qkv, p_o);
        // out projection
        gemm_tc<true, 0, false><<<dim3(4, 128), 256>>>(
            p_o, out_w + (size_t)l * 512 * 512, out_b + l * 512, nullptr,
            p_tmp, M, 512, 512);
        add_ln_kernel<<<16384, 256>>>(p_h, p_tmp, ln1_g + l * 512, ln1_b + l * 512, p_h);
        // feed-forward
        gemm_tc<true, 1, false><<<dim3(16, 128), 256>>>(
            p_h, ff1_w + (size_t)l * 2048 * 512, ff1_b + l * 2048, nullptr,
            p_ff, M, 2048, 512);
        gemm_tc<true, 0, false><<<dim3(4, 128), 256>>>(
            p_ff, ff2_w + (size_t)l * 512 * 2048, ff2_b + l * 512, nullptr,
            p_tmp, M, 512, 2048);
        add_ln_kernel<<<16384, 256>>>(p_h, p_tmp, ln2_g + l * 512, ln2_b + l * 512, p_h);
    }

    // memory attention: sims (3xTF32 for accuracy) -> softmax -> upd
    gemm_tc<true, 0, true><<<dim3(8, 128), 256>>>(p_h, memory, nullptr, nullptr,
                                                  attn_p, M, 1024, 512);
    softmax_kernel<4><<<16384, 256>>>(attn_p);
    gemm_tc<false, 0, false><<<dim3(4, 128), 256>>>(attn_p, memory, nullptr, nullptr,
                                                    p_upd, M, 512, 1024);
    // concat + fc1(relu) + fc2
    concat_kernel<<<(16384 * 128 + 255) / 256, 256>>>(p_h, p_upd, p_cat);
    gemm_tc<true, 1, false><<<dim3(4, 128), 256>>>(p_cat, fc1_w, fc1_b, nullptr,
                                                   p_t1, M, 512, 1024);
    gemm_tc<true, 0, false><<<dim3(1, 128), 256>>>(p_t1, fc2_w, fc2_b, nullptr,
                                                   t_out, M, 64, 512);

    // graph branch (exact fp32)
    feat_fn_kernel<<<32, 64>>>(x, p_fn);
    graph_adj_kernel<<<32, 64>>>(p_fn, p_An);
    gcn_gemm1_kernel<<<dim3(8, 32), 256>>>(x, gc1_w, gc1_b, p_gt1);
    an_mult_kernel<true, false><<<dim3(8, 32), 256>>>(p_An, p_gt1, p_gh1);
    gcn_gemm2_kernel<<<dim3(8, 32), 256>>>(p_gh1, gc2_w, gc2_b, p_gt1);
    an_mult_kernel<false, true><<<dim3(8, 32), 256>>>(p_An, p_gt1, gout_p);

    (void)in_sizes; (void)n_in; (void)out_size;
}

// round 5
// speedup vs baseline: 2.9094x; 1.1794x over previous
#include <cuda_runtime.h>
#include <math.h>
#include <stdint.h>

// ---------------------------------------------------------------------------
// Problem constants
//  B=32, S=512, F_IN=64, D=512, DFF=2048, MEM=1024, L=3, H=8, dh=64
//  rows = B*S = 16384
// ---------------------------------------------------------------------------

// ------------------------- static scratch buffers --------------------------
__device__ float g_pe[512 * 512];            // 1 MB
__device__ float g_h[16384 * 512];           // 32 MB
__device__ float g_tmp[16384 * 512];         // 32 MB
__device__ float g_qkv[16384 * 1536];        // 96 MB
__device__ float g_o[16384 * 512];           // 32 MB
__device__ float g_ff[16384 * 2048];         // 128 MB
__device__ float g_upd[16384 * 512];         // 32 MB
__device__ float g_cat[16384 * 1024];        // 64 MB
__device__ float g_t1[16384 * 512];          // 32 MB
__device__ float g_fn[32 * 64];
__device__ float g_An[32 * 64 * 64];
__device__ float g_gt1[32 * 64 * 512];       // 4 MB
__device__ float g_gh1[32 * 64 * 512];       // 4 MB

// ---------------------------------------------------------------------------
// tf32 helpers
// ---------------------------------------------------------------------------
__device__ __forceinline__ float tf32_rna(float x) {
    uint32_t u;
    asm("cvt.rna.tf32.f32 %0, %1;" : "=r"(u) : "f"(x));
    return __uint_as_float(u);
}

__device__ __forceinline__ void mma_tf32(float c[4],
    uint32_t a0, uint32_t a1, uint32_t a2, uint32_t a3,
    uint32_t b0, uint32_t b1)
{
    asm volatile(
        "mma.sync.aligned.m16n8k8.row.col.f32.tf32.tf32.f32 "
        "{%0,%1,%2,%3}, {%4,%5,%6,%7}, {%8,%9}, {%0,%1,%2,%3};"
        : "+f"(c[0]), "+f"(c[1]), "+f"(c[2]), "+f"(c[3])
        : "r"(a0), "r"(a1), "r"(a2), "r"(a3), "r"(b0), "r"(b1));
}

// ---------------------------------------------------------------------------
// Positional encoding (match numpy float64 -> float32)
// ---------------------------------------------------------------------------
__global__ void pe_kernel(float* __restrict__ pe) {
    int i = blockIdx.x * 256 + threadIdx.x;
    if (i >= 512 * 512) return;
    int s = i >> 9, d = i & 511;
    int t2 = d & ~1;
    double div = exp((double)t2 * (-9.210340371976184 / 512.0)); // ln(10000)
    double a = (double)s * div;
    pe[i] = (float)((d & 1) ? cos(a) : sin(a));
}

// ---------------------------------------------------------------------------
// Tensor-core GEMM: C[M,N] = A[M,K] * op(B) + bias (+relu / +pe)
//   TRANSB=true : B is (N,K) row-major  -> C = A @ B^T
//   TRANSB=false: B is (K,N) row-major  -> C = A @ B
//   SPLIT=true  : 3xTF32 (hi/lo split) for ~fp32 accuracy
// Block tile 128x128, 256 threads (8 warps = 2m x 4n of 64x32 warp tiles).
// EPI: 0 = bias, 1 = bias+relu, 2 = bias + positional encoding add
// ---------------------------------------------------------------------------
template <bool TRANSB, int EPI, bool SPLIT>
__global__ void __launch_bounds__(256) gemm_tc(
    const float* __restrict__ A, const float* __restrict__ B,
    const float* __restrict__ bias, const float* __restrict__ pe,
    float* __restrict__ C, int M, int N, int K)
{
    constexpr int KT   = SPLIT ? 16 : 32;
    constexpr int STR  = KT + 4;           // stride ≡ 4 (mod 32): conflict-free frags
    constexpr int TILE = 128 * STR;
    constexpr int KG   = KT / 4;           // float4 per row
    constexpr int ITS  = KT / 8;           // loader iterations (128*KG/256)

    __shared__ float As[(SPLIT ? 2 : 1) * TILE];
    __shared__ float Bs[(SPLIT ? 2 : 1) * TILE];

    const int tid  = threadIdx.x;
    const int lane = tid & 31, wid = tid >> 5;
    const int wm = (wid >> 2) * 64, wn = (wid & 3) * 32;
    const int r = lane >> 2, c = lane & 3;
    const int m0 = blockIdx.y * 128, n0 = blockIdx.x * 128;

    float acc[4][4][4];
#pragma unroll
    for (int i = 0; i < 4; i++)
#pragma unroll
        for (int j = 0; j < 4; j++)
#pragma unroll
            for (int t = 0; t < 4; t++) acc[i][j][t] = 0.f;

    for (int k0 = 0; k0 < K; k0 += KT) {
        // ---- load A tile (m-rows, k-cols), coalesced, tf32-converted ----
#pragma unroll
        for (int i = 0; i < ITS; i++) {
            int idx = tid + i * 256;
            int kg = idx & (KG - 1), m = idx / KG;
            float4 v = *reinterpret_cast<const float4*>(
                A + (size_t)(m0 + m) * K + k0 + kg * 4);
            float4 h;
            h.x = tf32_rna(v.x); h.y = tf32_rna(v.y);
            h.z = tf32_rna(v.z); h.w = tf32_rna(v.w);
            *reinterpret_cast<float4*>(&As[m * STR + kg * 4]) = h;
            if (SPLIT) {
                float4 l;
                l.x = tf32_rna(v.x - h.x); l.y = tf32_rna(v.y - h.y);
                l.z = tf32_rna(v.z - h.z); l.w = tf32_rna(v.w - h.w);
                *reinterpret_cast<float4*>(&As[TILE + m * STR + kg * 4]) = l;
            }
        }
        // ---- load B tile into Bs[n][k] ----
        if (TRANSB) {
#pragma unroll
            for (int i = 0; i < ITS; i++) {
                int idx = tid + i * 256;
                int kg = idx & (KG - 1), n = idx / KG;
                float4 v = make_float4(0.f, 0.f, 0.f, 0.f);
                if (n0 + n < N)
                    v = *reinterpret_cast<const float4*>(
                        B + (size_t)(n0 + n) * K + k0 + kg * 4);
                float4 h;
                h.x = tf32_rna(v.x); h.y = tf32_rna(v.y);
                h.z = tf32_rna(v.z); h.w = tf32_rna(v.w);
                *reinterpret_cast<float4*>(&Bs[n * STR + kg * 4]) = h;
                if (SPLIT) {
                    float4 l;
                    l.x = tf32_rna(v.x - h.x); l.y = tf32_rna(v.y - h.y);
                    l.z = tf32_rna(v.z - h.z); l.w = tf32_rna(v.w - h.w);
                    *reinterpret_cast<float4*>(&Bs[TILE + n * STR + kg * 4]) = l;
                }
            }
        } else {
#pragma unroll
            for (int i = 0; i < ITS; i++) {
                int idx = tid + i * 256;
                int ng = idx & 31, kk = idx >> 5;   // kk < KT
                int n = ng * 4;
                float4 v = make_float4(0.f, 0.f, 0.f, 0.f);
                if (n0 + n < N)
                    v = *reinterpret_cast<const float4*>(
                        B + (size_t)(k0 + kk) * N + n0 + n);
                float h0 = tf32_rna(v.x), h1 = tf32_rna(v.y);
                float h2 = tf32_rna(v.z), h3 = tf32_rna(v.w);
                Bs[(n + 0) * STR + kk] = h0; Bs[(n + 1) * STR + kk] = h1;
                Bs[(n + 2) * STR + kk] = h2; Bs[(n + 3) * STR + kk] = h3;
                if (SPLIT) {
                    Bs[TILE + (n + 0) * STR + kk] = tf32_rna(v.x - h0);
                    Bs[TILE + (n + 1) * STR + kk] = tf32_rna(v.y - h1);
                    Bs[TILE + (n + 2) * STR + kk] = tf32_rna(v.z - h2);
                    Bs[TILE + (n + 3) * STR + kk] = tf32_rna(v.w - h3);
                }
            }
        }
        __syncthreads();

#pragma unroll
        for (int ks = 0; ks < KT / 8; ks++) {
            const int kb = ks * 8 + c;
            uint32_t af[4][4], bf[4][2];
#pragma unroll
            for (int mi = 0; mi < 4; mi++) {
                const int mr = wm + mi * 16 + r;
                af[mi][0] = __float_as_uint(As[mr * STR + kb]);
                af[mi][1] = __float_as_uint(As[(mr + 8) * STR + kb]);
                af[mi][2] = __float_as_uint(As[mr * STR + kb + 4]);
                af[mi][3] = __float_as_uint(As[(mr + 8) * STR + kb + 4]);
            }
#pragma unroll
            for (int ni = 0; ni < 4; ni++) {
                const int nr = wn + ni * 8 + r;
                bf[ni][0] = __float_as_uint(Bs[nr * STR + kb]);
                bf[ni][1] = __float_as_uint(Bs[nr * STR + kb + 4]);
            }
#pragma unroll
            for (int mi = 0; mi < 4; mi++)
#pragma unroll
                for (int ni = 0; ni < 4; ni++)
                    mma_tf32(acc[mi][ni], af[mi][0], af[mi][1], af[mi][2], af[mi][3],
                             bf[ni][0], bf[ni][1]);
            if (SPLIT) {
                uint32_t afl[4][4], bfl[4][2];
#pragma unroll
                for (int mi = 0; mi < 4; mi++) {
                    const int mr = wm + mi * 16 + r;
                    afl[mi][0] = __float_as_uint(As[TILE + mr * STR + kb]);
                    afl[mi][1] = __float_as_uint(As[TILE + (mr + 8) * STR + kb]);
                    afl[mi][2] = __float_as_uint(As[TILE + mr * STR + kb + 4]);
                    afl[mi][3] = __float_as_uint(As[TILE + (mr + 8) * STR + kb + 4]);
                }
#pragma unroll
                for (int ni = 0; ni < 4; ni++) {
                    const int nr = wn + ni * 8 + r;
                    bfl[ni][0] = __float_as_uint(Bs[TILE + nr * STR + kb]);
                    bfl[ni][1] = __float_as_uint(Bs[TILE + nr * STR + kb + 4]);
                }
#pragma unroll
                for (int mi = 0; mi < 4; mi++)
#pragma unroll
                    for (int ni = 0; ni < 4; ni++) {
                        mma_tf32(acc[mi][ni], af[mi][0], af[mi][1], af[mi][2], af[mi][3],
                                 bfl[ni][0], bfl[ni][1]);
                        mma_tf32(acc[mi][ni], afl[mi][0], afl[mi][1], afl[mi][2], afl[mi][3],
                                 bf[ni][0], bf[ni][1]);
                    }
            }
        }
        __syncthreads();
    }

    // ---- epilogue ----
#pragma unroll
    for (int mi = 0; mi < 4; mi++) {
#pragma unroll
        for (int ni = 0; ni < 4; ni++) {
            const int row = m0 + wm + mi * 16 + r;
            const int col = n0 + wn + ni * 8 + 2 * c;
#pragma unroll
            for (int t = 0; t < 4; t++) {
                const int rr2 = row + (t >= 2 ? 8 : 0);
                const int cc2 = col + (t & 1);
                if (cc2 < N) {
                    float v = acc[mi][ni][t];
                    if (bias) v += __ldg(bias + cc2);
                    if (EPI == 1) v = fmaxf(v, 0.f);
                    if (EPI == 2) v += pe[((rr2 & 511) << 9) + cc2];
                    C[(size_t)rr2 * N + cc2] = v;
                }
            }
        }
    }
}

// ---------------------------------------------------------------------------
// Fused flash attention: o = softmax(QK^T/8) @ V, per (b,h), no score tensor.
// grid (8 qtile, 256 bh), 128 threads (4 warps, each owns 16 q-rows x 64).
// Dynamic smem: Qs(64x68) Ks(64x68) Ps(64x68) Vs(64x72) = 70656 B.
// ---------------------------------------------------------------------------
__global__ void __launch_bounds__(128) flash_attn_tc(
    const float* __restrict__ qkv, float* __restrict__ o)
{
    extern __shared__ float sm[];
    constexpr int STR  = 68;
    constexpr int VSTR = 72;
    float* Qs = sm;                     // [m][d]    64*68
    float* Ks = Qs + 64 * STR;          // [n][d]    64*68
    float* Ps = Ks + 64 * STR;          // [m][kpos] 64*68
    float* Vs = Ps + 64 * STR;          // [kpos][d] 64*72

    const int qt = blockIdx.x, bh = blockIdx.y;
    const int b = bh >> 3, h = bh & 7;
    const int tid = threadIdx.x, lane = tid & 31, wid = tid >> 5;
    const int wm = wid * 16;
    const int r = lane >> 2, c = lane & 3;

    // ---- load Q tile 64x64 (tf32) ----
#pragma unroll
    for (int i = 0; i < 8; i++) {
        int idx = tid + i * 128;
        int kg = idx & 15, m = idx >> 4;
        float4 v = *reinterpret_cast<const float4*>(
            qkv + (size_t)(b * 512 + qt * 64 + m) * 1536 + h * 64 + kg * 4);
        float4 hv;
        hv.x = tf32_rna(v.x); hv.y = tf32_rna(v.y);
        hv.z = tf32_rna(v.z); hv.w = tf32_rna(v.w);
        *reinterpret_cast<float4*>(&Qs[m * STR + kg * 4]) = hv;
    }

    float m_r[2] = {-3.402823466e38f, -3.402823466e38f};
    float l_r[2] = {0.f, 0.f};
    float oacc[8][4];
#pragma unroll
    for (int nf = 0; nf < 8; nf++)
#pragma unroll
        for (int t = 0; t < 4; t++) oacc[nf][t] = 0.f;

    for (int kc = 0; kc < 8; kc++) {
        // ---- load K chunk [n][d] and V chunk [kpos][d] (tf32) ----
#pragma unroll
        for (int i = 0; i < 8; i++) {
            int idx = tid + i * 128;
            int kg = idx & 15, m = idx >> 4;
            const float* base = qkv + (size_t)(b * 512 + kc * 64 + m) * 1536 + h * 64 + kg * 4;
            float4 kv = *reinterpret_cast<const float4*>(base + 512);
            float4 hk;
            hk.x = tf32_rna(kv.x); hk.y = tf32_rna(kv.y);
            hk.z = tf32_rna(kv.z); hk.w = tf32_rna(kv.w);
            *reinterpret_cast<float4*>(&Ks[m * STR + kg * 4]) = hk;
            float4 vv = *reinterpret_cast<const float4*>(base + 1024);
            float4 hvv;
            hvv.x = tf32_rna(vv.x); hvv.y = tf32_rna(vv.y);
            hvv.z = tf32_rna(vv.z); hvv.w = tf32_rna(vv.w);
            *reinterpret_cast<float4*>(&Vs[m * VSTR + kg * 4]) = hvv;
        }
        __syncthreads();

        // ---- S = Q K^T (warp tile 16x64), contraction over d=64 ----
        float sacc[8][4];
#pragma unroll
        for (int nf = 0; nf < 8; nf++)
#pragma unroll
            for (int t = 0; t < 4; t++) sacc[nf][t] = 0.f;

#pragma unroll
        for (int ks = 0; ks < 8; ks++) {
            const int kb = ks * 8 + c;
            uint32_t a0 = __float_as_uint(Qs[(wm + r) * STR + kb]);
            uint32_t a1 = __float_as_uint(Qs[(wm + r + 8) * STR + kb]);
            uint32_t a2 = __float_as_uint(Qs[(wm + r) * STR + kb + 4]);
            uint32_t a3 = __float_as_uint(Qs[(wm + r + 8) * STR + kb + 4]);
#pragma unroll
            for (int nf = 0; nf < 8; nf++) {
                const int nr = nf * 8 + r;
                uint32_t b0 = __float_as_uint(Ks[nr * STR + kb]);
                uint32_t b1 = __float_as_uint(Ks[nr * STR + kb + 4]);
                mma_tf32(sacc[nf], a0, a1, a2, a3, b0, b1);
            }
        }

        // ---- scale, row-max (rows r and r+8 of warp tile) ----
        float mx0 = -3.402823466e38f, mx1 = -3.402823466e38f;
#pragma unroll
        for (int nf = 0; nf < 8; nf++) {
#pragma unroll
            for (int t = 0; t < 4; t++) sacc[nf][t] *= 0.125f;
            mx0 = fmaxf(mx0, fmaxf(sacc[nf][0], sacc[nf][1]));
            mx1 = fmaxf(mx1, fmaxf(sacc[nf][2], sacc[nf][3]));
        }
        mx0 = fmaxf(mx0, __shfl_xor_sync(0xffffffffu, mx0, 1));
        mx0 = fmaxf(mx0, __shfl_xor_sync(0xffffffffu, mx0, 2));
        mx1 = fmaxf(mx1, __shfl_xor_sync(0xffffffffu, mx1, 1));
        mx1 = fmaxf(mx1, __shfl_xor_sync(0xffffffffu, mx1, 2));

        const float mn0 = fmaxf(m_r[0], mx0);
        const float mn1 = fmaxf(m_r[1], mx1);
        const float f0 = expf(m_r[0] - mn0);
        const float f1 = expf(m_r[1] - mn1);

        // ---- P = exp(S - m), row-sum, store P (tf32) to smem ----
        float s0 = 0.f, s1 = 0.f;
#pragma unroll
        for (int nf = 0; nf < 8; nf++) {
            float p0 = expf(sacc[nf][0] - mn0);
            float p1 = expf(sacc[nf][1] - mn0);
            float p2 = expf(sacc[nf][2] - mn1);
            float p3 = expf(sacc[nf][3] - mn1);
            s0 += p0 + p1;
            s1 += p2 + p3;
            float2 q01 = make_float2(tf32_rna(p0), tf32_rna(p1));
            float2 q23 = make_float2(tf32_rna(p2), tf32_rna(p3));
            *reinterpret_cast<float2*>(&Ps[(wm + r) * STR + nf * 8 + 2 * c]) = q01;
            *reinterpret_cast<float2*>(&Ps[(wm + r + 8) * STR + nf * 8 + 2 * c]) = q23;
            // rescale running output
            oacc[nf][0] *= f0; oacc[nf][1] *= f0;
            oacc[nf][2] *= f1; oacc[nf][3] *= f1;
        }
        s0 += __shfl_xor_sync(0xffffffffu, s0, 1);
        s0 += __shfl_xor_sync(0xffffffffu, s0, 2);
        s1 += __shfl_xor_sync(0xffffffffu, s1, 1);
        s1 += __shfl_xor_sync(0xffffffffu, s1, 2);
        l_r[0] = l_r[0] * f0 + s0;
        l_r[1] = l_r[1] * f1 + s1;
        m_r[0] = mn0; m_r[1] = mn1;
        __syncwarp();

        // ---- O += P @ V, contraction over kpos=64 ----
#pragma unroll
        for (int ks = 0; ks < 8; ks++) {
            const int kb = ks * 8 + c;
            uint32_t a0 = __float_as_uint(Ps[(wm + r) * STR + kb]);
            uint32_t a1 = __float_as_uint(Ps[(wm + r + 8) * STR + kb]);
            uint32_t a2 = __float_as_uint(Ps[(wm + r) * STR + kb + 4]);
            uint32_t a3 = __float_as_uint(Ps[(wm + r + 8) * STR + kb + 4]);
#pragma unroll
            for (int nf = 0; nf < 8; nf++) {
                const int nr = nf * 8 + r;
                uint32_t b0 = __float_as_uint(Vs[kb * VSTR + nr]);
                uint32_t b1 = __float_as_uint(Vs[(kb + 4) * VSTR + nr]);
                mma_tf32(oacc[nf], a0, a1, a2, a3, b0, b1);
            }
        }
        __syncthreads();
    }

    // ---- epilogue: divide by l, write o[b, q, h*64+d] ----
    const float inv0 = 1.f / l_r[0];
    const float inv1 = 1.f / l_r[1];
#pragma unroll
    for (int nf = 0; nf < 8; nf++) {
        const int row = qt * 64 + wm + r;
        const int col = nf * 8 + 2 * c;
        float* ob = o + (size_t)(b * 512 + row) * 512 + h * 64 + col;
        ob[0]           = oacc[nf][0] * inv0;
        ob[1]           = oacc[nf][1] * inv0;
        ob[8 * 512]     = oacc[nf][2] * inv1;
        ob[8 * 512 + 1] = oacc[nf][3] * inv1;
    }
}

// ---------------------------------------------------------------------------
// Row softmax, row length = CPT*256, one block of 256 threads per row
// ---------------------------------------------------------------------------
template <int CPT>
__global__ void __launch_bounds__(256) softmax_kernel(float* __restrict__ data)
{
    float* row = data + (size_t)blockIdx.x * (CPT * 256);
    const int tid = threadIdx.x;
    float x[CPT];
    float mx = -3.402823466e38f;
#pragma unroll
    for (int c = 0; c < CPT; c++) {
        x[c] = row[tid + 256 * c];
        mx = fmaxf(mx, x[c]);
    }
    __shared__ float sh[8];
#pragma unroll
    for (int o = 16; o; o >>= 1) mx = fmaxf(mx, __shfl_xor_sync(0xffffffffu, mx, o));
    if ((tid & 31) == 0) sh[tid >> 5] = mx;
    __syncthreads();
    mx = sh[0];
#pragma unroll
    for (int w = 1; w < 8; w++) mx = fmaxf(mx, sh[w]);

    float s = 0.f;
#pragma unroll
    for (int c = 0; c < CPT; c++) { x[c] = expf(x[c] - mx); s += x[c]; }
    __syncthreads();
#pragma unroll
    for (int o = 16; o; o >>= 1) s += __shfl_xor_sync(0xffffffffu, s, o);
    if ((tid & 31) == 0) sh[tid >> 5] = s;
    __syncthreads();
    float tot = sh[0];
#pragma unroll
    for (int w = 1; w < 8; w++) tot += sh[w];
    float inv = 1.f / tot;
#pragma unroll
    for (int c = 0; c < CPT; c++) row[tid + 256 * c] = x[c] * inv;
}

// ---------------------------------------------------------------------------
// out = LayerNorm(X + Y) * g + b  (row length 512, one block per row)
// ---------------------------------------------------------------------------
__global__ void __launch_bounds__(256) add_ln_kernel(
    const float* __restrict__ X, const float* __restrict__ Y,
    const float* __restrict__ gam, const float* __restrict__ bet,
    float* __restrict__ out)
{
    const size_t row = blockIdx.x;
    const float* xr = X + row * 512;
    const float* yr = Y + row * 512;
    const int tid = threadIdx.x;
    float t0 = xr[tid] + yr[tid];
    float t1 = xr[tid + 256] + yr[tid + 256];

    __shared__ float sh[8];
    float s = t0 + t1;
#pragma unroll
    for (int o = 16; o; o >>= 1) s += __shfl_xor_sync(0xffffffffu, s, o);
    if ((tid & 31) == 0) sh[tid >> 5] = s;
    __syncthreads();
    float tot = sh[0];
#pragma unroll
    for (int w = 1; w < 8; w++) tot += sh[w];
    float mean = tot * (1.f / 512.f);
    float d0 = t0 - mean, d1 = t1 - mean;
    float q = d0 * d0 + d1 * d1;
    __syncthreads();
#pragma unroll
    for (int o = 16; o; o >>= 1) q += __shfl_xor_sync(0xffffffffu, q, o);
    if ((tid & 31) == 0) sh[tid >> 5] = q;
    __syncthreads();
    float vtot = sh[0];
#pragma unroll
    for (int w = 1; w < 8; w++) vtot += sh[w];
    float inv = rsqrtf(vtot * (1.f / 512.f) + 1e-5f);
    float* orow = out + row * 512;
    orow[tid] = d0 * inv * gam[tid] + bet[tid];
    orow[tid + 256] = d1 * inv * gam[tid + 256] + bet[tid + 256];
}

// ---------------------------------------------------------------------------
// cat = [h | upd]  (16384 x 1024)
// ---------------------------------------------------------------------------
__global__ void concat_kernel(const float* __restrict__ a,
                              const float* __restrict__ b,
                              float* __restrict__ c)
{
    size_t i = (size_t)blockIdx.x * 256 + threadIdx.x;
    if (i >= (size_t)16384 * 128) return; // float4 count per half
    size_t r = i >> 7, col = i & 127;
    const float4* a4 = reinterpret_cast<const float4*>(a);
    const float4* b4 = reinterpret_cast<const float4*>(b);
    float4* c4 = reinterpret_cast<float4*>(c);
    c4[r * 256 + col] = a4[i];
    c4[r * 256 + 128 + col] = b4[i];
}

// ---------------------------------------------------------------------------
// Graph branch (exact fp32, tiny cost)
// ---------------------------------------------------------------------------
__global__ void feat_fn_kernel(const float* __restrict__ x, float* __restrict__ fn)
{
    const int b = blockIdx.x, i = threadIdx.x; // 64 threads
    const float* xp = x + (size_t)b * 32768 + i;
    float s = 0.f;
    for (int t = 0; t < 512; t++) s += xp[(size_t)t * 64];
    float f = s * (1.f / 512.f);
    __shared__ float sh[64];
    sh[i] = f * f;
    __syncthreads();
    for (int o = 32; o; o >>= 1) {
        if (i < o) sh[i] += sh[i + o];
        __syncthreads();
    }
    float norm = sqrtf(sh[0]);
    fn[b * 64 + i] = f / fmaxf(norm, 1e-12f);
}

__global__ void graph_adj_kernel(const float* __restrict__ fn, float* __restrict__ An)
{
    const int b = blockIdx.x, i = threadIdx.x; // 64 threads
    __shared__ float f[64];
    __shared__ unsigned char A[64][64];
    f[i] = fn[b * 64 + i];
    for (int j = 0; j < 64; j++) A[i][j] = 0;
    __syncthreads();
    const float fi = f[i];
    float bv0 = -3.402823466e38f, bv1 = bv0, bv2 = bv0, bv3 = bv0;
    int i0 = 0, i1 = 0, i2 = 0, i3 = 0;
    for (int j = 0; j < 64; j++) {
        float v = fi * f[j];
        if (v > bv3) {
            if (v > bv0)      { bv3 = bv2; i3 = i2; bv2 = bv1; i2 = i1; bv1 = bv0; i1 = i0; bv0 = v; i0 = j; }
            else if (v > bv1) { bv3 = bv2; i3 = i2; bv2 = bv1; i2 = i1; bv1 = v; i1 = j; }
            else if (v > bv2) { bv3 = bv2; i3 = i2; bv2 = v; i2 = j; }
            else              { bv3 = v; i3 = j; }
        }
    }
    A[i][i1] = 1; A[i][i2] = 1; A[i][i3] = 1;
    __syncthreads();
    float deg = 0.f;
    for (int j = 0; j < 64; j++) {
        bool a = (j == i) || A[i][j] || A[j][i];
        deg += a ? 1.f : 0.f;
    }
    float inv = 1.f / deg;
    float* row = An + (size_t)b * 4096 + i * 64;
    for (int j = 0; j < 64; j++) {
        bool a = (j == i) || A[i][j] || A[j][i];
        row[j] = a ? inv : 0.f;
    }
}

// t1[b,f,d] = sum_s x[b,s,f] * w[d,s] + bias[d]   (M=64 f, N=512 d, K=512 s)
__global__ void __launch_bounds__(256) gcn_gemm1_kernel(
    const float* __restrict__ x, const float* __restrict__ w,
    const float* __restrict__ bias, float* __restrict__ out)
{
    const int dt = blockIdx.x, b = blockIdx.y;
    __shared__ float Xs[16][64];
    __shared__ float Ws[64][17];
    const int tid = threadIdx.x, tx = tid & 15, ty = tid >> 4;
    float acc[4][4];
#pragma unroll
    for (int i = 0; i < 4; i++)
#pragma unroll
        for (int j = 0; j < 4; j++) acc[i][j] = 0.f;

    for (int k0 = 0; k0 < 512; k0 += 16) {
        {
            int kk = tid >> 4, f4 = (tid & 15) << 2;
            float4 v = *reinterpret_cast<const float4*>(
                x + (size_t)b * 32768 + (size_t)(k0 + kk) * 64 + f4);
            *reinterpret_cast<float4*>(&Xs[kk][f4]) = v;
            int dd = tid >> 2, k4 = (tid & 3) << 2;
            float4 w4 = *reinterpret_cast<const float4*>(
                w + (size_t)(dt * 64 + dd) * 512 + k0 + k4);
            Ws[dd][k4 + 0] = w4.x; Ws[dd][k4 + 1] = w4.y;
            Ws[dd][k4 + 2] = w4.z; Ws[dd][k4 + 3] = w4.w;
        }
        __syncthreads();
#pragma unroll
        for (int kk = 0; kk < 16; kk++) {
            float a[4], bb[4];
#pragma unroll
            for (int i = 0; i < 4; i++) a[i] = Xs[kk][ty + 16 * i];
#pragma unroll
            for (int j = 0; j < 4; j++) bb[j] = Ws[tx + 16 * j][kk];
#pragma unroll
            for (int i = 0; i < 4; i++)
#pragma unroll
                for (int j = 0; j < 4; j++)
                    acc[i][j] = fmaf(a[i], bb[j], acc[i][j]);
        }
        __syncthreads();
    }
#pragma unroll
    for (int i = 0; i < 4; i++)
#pragma unroll
        for (int j = 0; j < 4; j++) {
            int dd = dt * 64 + tx + 16 * j;
            out[(size_t)b * 32768 + (size_t)(ty + 16 * i) * 512 + dd] =
                acc[i][j] + bias[dd];
        }
}

// t2[b,f,s] = sum_d Ain[b,f,d] * w[s,d] + bias[s]
__global__ void __launch_bounds__(256) gcn_gemm2_kernel(
    const float* __restrict__ Ain, const float* __restrict__ w,
    const float* __restrict__ bias, float* __restrict__ out)
{
    const int st = blockIdx.x, b = blockIdx.y;
    __shared__ float As[64][17];
    __shared__ float Ws[64][17];
    const int tid = threadIdx.x, tx = tid & 15, ty = tid >> 4;
    const int rr = tid >> 2, k4 = (tid & 3) << 2;
    float acc[4][4];
#pragma unroll
    for (int i = 0; i < 4; i++)
#pragma unroll
        for (int j = 0; j < 4; j++) acc[i][j] = 0.f;

    for (int k0 = 0; k0 < 512; k0 += 16) {
        float4 a4 = *reinterpret_cast<const float4*>(
            Ain + (size_t)b * 32768 + (size_t)rr * 512 + k0 + k4);
        As[rr][k4 + 0] = a4.x; As[rr][k4 + 1] = a4.y;
        As[rr][k4 + 2] = a4.z; As[rr][k4 + 3] = a4.w;
        float4 w4 = *reinterpret_cast<const float4*>(
            w + (size_t)(st * 64 + rr) * 512 + k0 + k4);
        Ws[rr][k4 + 0] = w4.x; Ws[rr][k4 + 1] = w4.y;
        Ws[rr][k4 + 2] = w4.z; Ws[rr][k4 + 3] = w4.w;
        __syncthreads();
#pragma unroll
        for (int kk = 0; kk < 16; kk++) {
            float a[4], bb[4];
#pragma unroll
            for (int i = 0; i < 4; i++) a[i] = As[ty + 16 * i][kk];
#pragma unroll
            for (int j = 0; j < 4; j++) bb[j] = Ws[tx + 16 * j][kk];
#pragma unroll
            for (int i = 0; i < 4; i++)
#pragma unroll
                for (int j = 0; j < 4; j++)
                    acc[i][j] = fmaf(a[i], bb[j], acc[i][j]);
        }
        __syncthreads();
    }
#pragma unroll
    for (int i = 0; i < 4; i++)
#pragma unroll
        for (int j = 0; j < 4; j++) {
            int ss = st * 64 + tx + 16 * j;
            out[(size_t)b * 32768 + (size_t)(ty + 16 * i) * 512 + ss] =
                acc[i][j] + bias[ss];
        }
}

// out = (relu?) An @ in ; optional transposed write g_out[b, s, f]
template <bool RELU, bool TRANSOUT>
__global__ void __launch_bounds__(256) an_mult_kernel(
    const float* __restrict__ An, const float* __restrict__ in,
    float* __restrict__ out)
{
    const int dt = blockIdx.x, b = blockIdx.y;
    __shared__ float As[64][65];
    __shared__ float Ins[64][64];
    const int tid = threadIdx.x, tx = tid & 15, ty = tid >> 4;

    for (int t = tid; t < 4096; t += 256)
        As[t >> 6][t & 63] = An[(size_t)b * 4096 + t];
#pragma unroll
    for (int hh = 0; hh < 4; hh++) {
        int idx4 = tid + hh * 256;
        int gg = idx4 >> 4, c4 = (idx4 & 15) << 2;
        float4 v = *reinterpret_cast<const float4*>(
            in + (size_t)b * 32768 + (size_t)gg * 512 + dt * 64 + c4);
        *reinterpret_cast<float4*>(&Ins[gg][c4]) = v;
    }
    __syncthreads();

    float acc[4][4];
#pragma unroll
    for (int i = 0; i < 4; i++)
#pragma unroll
        for (int j = 0; j < 4; j++) acc[i][j] = 0.f;

#pragma unroll 8
    for (int kk = 0; kk < 64; kk++) {
        float a[4], bb[4];
#pragma unroll
        for (int i = 0; i < 4; i++) a[i] = As[ty + 16 * i][kk];
#pragma unroll
        for (int j = 0; j < 4; j++) bb[j] = Ins[kk][tx + 16 * j];
#pragma unroll
        for (int i = 0; i < 4; i++)
#pragma unroll
            for (int j = 0; j < 4; j++)
                acc[i][j] = fmaf(a[i], bb[j], acc[i][j]);
    }

#pragma unroll
    for (int i = 0; i < 4; i++)
#pragma unroll
        for (int j = 0; j < 4; j++) {
            int ff = ty + 16 * i;
            int dd = dt * 64 + tx + 16 * j;
            float v = acc[i][j];
            if (RELU) v = fmaxf(v, 0.f);
            if (!TRANSOUT)
                out[(size_t)b * 32768 + (size_t)ff * 512 + dd] = v;
            else
                out[(size_t)b * 32768 + (size_t)dd * 64 + ff] = v;
        }
}

// ---------------------------------------------------------------------------
// Host orchestration
// ---------------------------------------------------------------------------
extern "C" void kernel_launch(void* const* d_in, const int* in_sizes, int n_in,
                              void* d_out, int out_size)
{
    const float* x      = (const float*)d_in[0];
    const float* W_in   = (const float*)d_in[1];
    const float* b_in   = (const float*)d_in[2];
    const float* qkv_w  = (const float*)d_in[3];
    const float* qkv_b  = (const float*)d_in[4];
    const float* out_w  = (const float*)d_in[5];
    const float* out_b  = (const float*)d_in[6];
    const float* ln1_g  = (const float*)d_in[7];
    const float* ln1_b  = (const float*)d_in[8];
    const float* ln2_g  = (const float*)d_in[9];
    const float* ln2_b  = (const float*)d_in[10];
    const float* ff1_w  = (const float*)d_in[11];
    const float* ff1_b  = (const float*)d_in[12];
    const float* ff2_w  = (const float*)d_in[13];
    const float* ff2_b  = (const float*)d_in[14];
    const float* memory = (const float*)d_in[15];
    const float* fc1_w  = (const float*)d_in[16];
    const float* fc1_b  = (const float*)d_in[17];
    const float* fc2_w  = (const float*)d_in[18];
    const float* fc2_b  = (const float*)d_in[19];
    const float* gc1_w  = (const float*)d_in[20];
    const float* gc1_b  = (const float*)d_in[21];
    const float* gc2_w  = (const float*)d_in[22];
    const float* gc2_b  = (const float*)d_in[23];

    float* out    = (float*)d_out;
    float* t_out  = out;                       // (32,512,64)
    float* gout_p = out + 1048576;             // (32,512,64)
    float* attn_p = out + 2097152;             // (32,512,1024)

    const int FA_SMEM = (3 * 68 + 72) * 64 * 4;   // 70656 bytes

    static float *p_pe = nullptr, *p_h, *p_tmp, *p_qkv, *p_o, *p_ff,
                 *p_upd, *p_cat, *p_t1, *p_fn, *p_An, *p_gt1, *p_gh1;
    if (!p_pe) {
        cudaGetSymbolAddress((void**)&p_pe,  g_pe);
        cudaGetSymbolAddress((void**)&p_h,   g_h);
        cudaGetSymbolAddress((void**)&p_tmp, g_tmp);
        cudaGetSymbolAddress((void**)&p_qkv, g_qkv);
        cudaGetSymbolAddress((void**)&p_o,   g_o);
        cudaGetSymbolAddress((void**)&p_ff,  g_ff);
        cudaGetSymbolAddress((void**)&p_upd, g_upd);
        cudaGetSymbolAddress((void**)&p_cat, g_cat);
        cudaGetSymbolAddress((void**)&p_t1,  g_t1);
        cudaGetSymbolAddress((void**)&p_fn,  g_fn);
        cudaGetSymbolAddress((void**)&p_An,  g_An);
        cudaGetSymbolAddress((void**)&p_gt1, g_gt1);
        cudaGetSymbolAddress((void**)&p_gh1, g_gh1);
        cudaFuncSetAttribute(flash_attn_tc,
                             cudaFuncAttributeMaxDynamicSharedMemorySize, FA_SMEM);
    }

    const int M = 16384;

    // positional encoding
    pe_kernel<<<(512 * 512 + 255) / 256, 256>>>(p_pe);

    // h = x @ W_in^T + b_in + pe
    gemm_tc<true, 2, false><<<dim3(4, 128), 256>>>(x, W_in, b_in, p_pe, p_h, M, 512, 64);

    for (int l = 0; l < 3; l++) {
        // qkv
        gemm_tc<true, 0, false><<<dim3(12, 128), 256>>>(
            p_h, qkv_w + (size_t)l * 1536 * 512, qkv_b + l * 1536, nullptr,
            p_qkv, M, 1536, 512);
        // fused attention (scores + softmax + att@v, no materialized scores)
        flash_attn_tc<<<dim3(8, 256), 128, FA_SMEM>>>(p_qkv, p_o);
        // out projection
        gemm_tc<true, 0, false><<<dim3(4, 128), 256>>>(
            p_o, out_w + (size_t)l * 512 * 512, out_b + l * 512, nullptr,
            p_tmp, M, 512, 512);
        add_ln_kernel<<<16384, 256>>>(p_h, p_tmp, ln1_g + l * 512, ln1_b + l * 512, p_h);
        // feed-forward
        gemm_tc<true, 1, false><<<dim3(16, 128), 256>>>(
            p_h, ff1_w + (size_t)l * 2048 * 512, ff1_b + l * 2048, nullptr,
            p_ff, M, 2048, 512);
        gemm_tc<true, 0, false><<<dim3(4, 128), 256>>>(
            p_ff, ff2_w + (size_t)l * 512 * 2048, ff2_b + l * 512, nullptr,
            p_tmp, M, 512, 2048);
        add_ln_kernel<<<16384, 256>>>(p_h, p_tmp, ln2_g + l * 512, ln2_b + l * 512, p_h);
    }

    // memory attention: sims (3xTF32 for accuracy) -> softmax -> upd
    gemm_tc<true, 0, true><<<dim3(8, 128), 256>>>(p_h, memory, nullptr, nullptr,
                                                  attn_p, M, 1024, 512);
    softmax_kernel<4><<<16384, 256>>>(attn_p);
    gemm_tc<false, 0, false><<<dim3(4, 128), 256>>>(attn_p, memory, nullptr, nullptr,
                                                    p_upd, M, 512, 1024);
    // concat + fc1(relu) + fc2
    concat_kernel<<<(16384 * 128 + 255) / 256, 256>>>(p_h, p_upd, p_cat);
    gemm_tc<true, 1, false><<<dim3(4, 128), 256>>>(p_cat, fc1_w, fc1_b, nullptr,
                                                   p_t1, M, 512, 1024);
    gemm_tc<true, 0, false><<<dim3(1, 128), 256>>>(p_t1, fc2_w, fc2_b, nullptr,
                                                   t_out, M, 64, 512);

    // graph branch (exact fp32)
    feat_fn_kernel<<<32, 64>>>(x, p_fn);
    graph_adj_kernel<<<32, 64>>>(p_fn, p_An);
    gcn_gemm1_kernel<<<dim3(8, 32), 256>>>(x, gc1_w, gc1_b, p_gt1);
    an_mult_kernel<true, false><<<dim3(8, 32), 256>>>(p_An, p_gt1, p_gh1);
    gcn_gemm2_kernel<<<dim3(8, 32), 256>>>(p_gh1, gc2_w, gc2_b, p_gt1);
    an_mult_kernel<false, true><<<dim3(8, 32), 256>>>(p_An, p_gt1, gout_p);

    (void)in_sizes; (void)n_in; (void)out_size;
}

// round 6
// speedup vs baseline: 3.1097x; 1.0688x over previous
#include <cuda_runtime.h>
#include <math.h>
#include <stdint.h>

// ---------------------------------------------------------------------------
// Problem constants
//  B=32, S=512, F_IN=64, D=512, DFF=2048, MEM=1024, L=3, H=8, dh=64
//  rows = B*S = 16384
// ---------------------------------------------------------------------------

// ------------------------- static scratch buffers --------------------------
__device__ float g_pe[512 * 512];            // 1 MB
__device__ float g_h[16384 * 512];           // 32 MB
__device__ float g_tmp[16384 * 512];         // 32 MB
__device__ float g_qkv[16384 * 1536];        // 96 MB
__device__ float g_o[16384 * 512];           // 32 MB
__device__ float g_ff[16384 * 2048];         // 128 MB
__device__ float g_upd[16384 * 512];         // 32 MB
__device__ float g_t1[16384 * 512];          // 32 MB
__device__ float g_fn[32 * 64];
__device__ float g_An[32 * 64 * 64];
__device__ float g_gt1[32 * 64 * 512];       // 4 MB
__device__ float g_gh1[32 * 64 * 512];       // 4 MB

// ---------------------------------------------------------------------------
// tf32 helpers
// ---------------------------------------------------------------------------
__device__ __forceinline__ float tf32_rna(float x) {
    uint32_t u;
    asm("cvt.rna.tf32.f32 %0, %1;" : "=r"(u) : "f"(x));
    return __uint_as_float(u);
}

__device__ __forceinline__ void mma_tf32(float c[4],
    uint32_t a0, uint32_t a1, uint32_t a2, uint32_t a3,
    uint32_t b0, uint32_t b1)
{
    asm volatile(
        "mma.sync.aligned.m16n8k8.row.col.f32.tf32.tf32.f32 "
        "{%0,%1,%2,%3}, {%4,%5,%6,%7}, {%8,%9}, {%0,%1,%2,%3};"
        : "+f"(c[0]), "+f"(c[1]), "+f"(c[2]), "+f"(c[3])
        : "r"(a0), "r"(a1), "r"(a2), "r"(a3), "r"(b0), "r"(b1));
}

// ---------------------------------------------------------------------------
// Positional encoding (match numpy float64 -> float32)
// ---------------------------------------------------------------------------
__global__ void pe_kernel(float* __restrict__ pe) {
    int i = blockIdx.x * 256 + threadIdx.x;
    if (i >= 512 * 512) return;
    int s = i >> 9, d = i & 511;
    int t2 = d & ~1;
    double div = exp((double)t2 * (-9.210340371976184 / 512.0)); // ln(10000)
    double a = (double)s * div;
    pe[i] = (float)((d & 1) ? cos(a) : sin(a));
}

// ---------------------------------------------------------------------------
// Tensor-core GEMM, register-staged software pipeline.
//  C[M,N] = A[M,K] * op(B) + bias (+relu / +pe)
//   TRANSB=true : B is (N,K) row-major  -> C = A @ B^T
//   TRANSB=false: B is (K,N) row-major  -> C = A @ B
//   SPLIT=true  : 3xTF32 (hi/lo split) for ~fp32 accuracy
//   CATAB=true  : A is logical [M, 1024] = concat(A[:,0:512], A2[:,0:512])
// Block tile 128x128, 256 threads (8 warps = 2m x 4n of 64x32 warp tiles).
// EPI: 0 = bias, 1 = bias+relu, 2 = bias + positional encoding add
// ---------------------------------------------------------------------------
template <bool TRANSB, int EPI, bool SPLIT, bool CATAB = false>
__global__ void __launch_bounds__(256) gemm_tc(
    const float* __restrict__ A, const float* __restrict__ A2,
    const float* __restrict__ B,
    const float* __restrict__ bias, const float* __restrict__ pe,
    float* __restrict__ C, int M, int N, int K)
{
    constexpr int KT   = SPLIT ? 16 : 32;
    constexpr int STR  = KT + 4;           // stride ≡ 4 (mod 32): conflict-free frags
    constexpr int TILE = 128 * STR;
    constexpr int KG   = KT / 4;           // float4 per row
    constexpr int ITS  = KT / 8;           // loader iterations (128*KG/256)

    __shared__ float As[(SPLIT ? 2 : 1) * TILE];
    __shared__ float Bs[(SPLIT ? 2 : 1) * TILE];

    const int tid  = threadIdx.x;
    const int lane = tid & 31, wid = tid >> 5;
    const int wm = (wid >> 2) * 64, wn = (wid & 3) * 32;
    const int r = lane >> 2, c = lane & 3;
    const int m0 = blockIdx.y * 128, n0 = blockIdx.x * 128;

    float4 rA[ITS], rB[ITS];

    // ---- prefetch tile k0 into registers ----
    auto load_regs = [&](int k0) {
#pragma unroll
        for (int i = 0; i < ITS; i++) {
            int idx = tid + i * 256;
            int kg = idx & (KG - 1), m = idx / KG;
            const float* Ap = A;
            int lda = K, kcol = k0 + kg * 4;
            if (CATAB) {
                lda = 512;
                if (k0 >= 512) { Ap = A2; kcol -= 512; }
            }
            rA[i] = *reinterpret_cast<const float4*>(
                Ap + (size_t)(m0 + m) * lda + kcol);
        }
        if (TRANSB) {
#pragma unroll
            for (int i = 0; i < ITS; i++) {
                int idx = tid + i * 256;
                int kg = idx & (KG - 1), n = idx / KG;
                rB[i] = make_float4(0.f, 0.f, 0.f, 0.f);
                if (n0 + n < N)
                    rB[i] = *reinterpret_cast<const float4*>(
                        B + (size_t)(n0 + n) * K + k0 + kg * 4);
            }
        } else {
#pragma unroll
            for (int i = 0; i < ITS; i++) {
                int idx = tid + i * 256;
                int ng = idx & 31, kk = idx >> 5;
                int n = ng * 4;
                rB[i] = make_float4(0.f, 0.f, 0.f, 0.f);
                if (n0 + n < N)
                    rB[i] = *reinterpret_cast<const float4*>(
                        B + (size_t)(k0 + kk) * N + n0 + n);
            }
        }
    };

    auto store_smem = [&]() {
#pragma unroll
        for (int i = 0; i < ITS; i++) {
            int idx = tid + i * 256;
            int kg = idx & (KG - 1), m = idx / KG;
            float4 v = rA[i];
            float4 h;
            h.x = tf32_rna(v.x); h.y = tf32_rna(v.y);
            h.z = tf32_rna(v.z); h.w = tf32_rna(v.w);
            *reinterpret_cast<float4*>(&As[m * STR + kg * 4]) = h;
            if (SPLIT) {
                float4 l;
                l.x = tf32_rna(v.x - h.x); l.y = tf32_rna(v.y - h.y);
                l.z = tf32_rna(v.z - h.z); l.w = tf32_rna(v.w - h.w);
                *reinterpret_cast<float4*>(&As[TILE + m * STR + kg * 4]) = l;
            }
        }
        if (TRANSB) {
#pragma unroll
            for (int i = 0; i < ITS; i++) {
                int idx = tid + i * 256;
                int kg = idx & (KG - 1), n = idx / KG;
                float4 v = rB[i];
                float4 h;
                h.x = tf32_rna(v.x); h.y = tf32_rna(v.y);
                h.z = tf32_rna(v.z); h.w = tf32_rna(v.w);
                *reinterpret_cast<float4*>(&Bs[n * STR + kg * 4]) = h;
                if (SPLIT) {
                    float4 l;
                    l.x = tf32_rna(v.x - h.x); l.y = tf32_rna(v.y - h.y);
                    l.z = tf32_rna(v.z - h.z); l.w = tf32_rna(v.w - h.w);
                    *reinterpret_cast<float4*>(&Bs[TILE + n * STR + kg * 4]) = l;
                }
            }
        } else {
#pragma unroll
            for (int i = 0; i < ITS; i++) {
                int idx = tid + i * 256;
                int ng = idx & 31, kk = idx >> 5;
                int n = ng * 4;
                float4 v = rB[i];
                float h0 = tf32_rna(v.x), h1 = tf32_rna(v.y);
                float h2 = tf32_rna(v.z), h3 = tf32_rna(v.w);
                Bs[(n + 0) * STR + kk] = h0; Bs[(n + 1) * STR + kk] = h1;
                Bs[(n + 2) * STR + kk] = h2; Bs[(n + 3) * STR + kk] = h3;
                if (SPLIT) {
                    Bs[TILE + (n + 0) * STR + kk] = tf32_rna(v.x - h0);
                    Bs[TILE + (n + 1) * STR + kk] = tf32_rna(v.y - h1);
                    Bs[TILE + (n + 2) * STR + kk] = tf32_rna(v.z - h2);
                    Bs[TILE + (n + 3) * STR + kk] = tf32_rna(v.w - h3);
                }
            }
        }
    };

    float acc[4][4][4];
#pragma unroll
    for (int i = 0; i < 4; i++)
#pragma unroll
        for (int j = 0; j < 4; j++)
#pragma unroll
            for (int t = 0; t < 4; t++) acc[i][j][t] = 0.f;

    load_regs(0);

    for (int k0 = 0; k0 < K; k0 += KT) {
        store_smem();
        __syncthreads();
        if (k0 + KT < K) load_regs(k0 + KT);   // overlap with MMA below

#pragma unroll
        for (int ks = 0; ks < KT / 8; ks++) {
            const int kb = ks * 8 + c;
            uint32_t af[4][4], bf[4][2];
#pragma unroll
            for (int mi = 0; mi < 4; mi++) {
                const int mr = wm + mi * 16 + r;
                af[mi][0] = __float_as_uint(As[mr * STR + kb]);
                af[mi][1] = __float_as_uint(As[(mr + 8) * STR + kb]);
                af[mi][2] = __float_as_uint(As[mr * STR + kb + 4]);
                af[mi][3] = __float_as_uint(As[(mr + 8) * STR + kb + 4]);
            }
#pragma unroll
            for (int ni = 0; ni < 4; ni++) {
                const int nr = wn + ni * 8 + r;
                bf[ni][0] = __float_as_uint(Bs[nr * STR + kb]);
                bf[ni][1] = __float_as_uint(Bs[nr * STR + kb + 4]);
            }
#pragma unroll
            for (int mi = 0; mi < 4; mi++)
#pragma unroll
                for (int ni = 0; ni < 4; ni++)
                    mma_tf32(acc[mi][ni], af[mi][0], af[mi][1], af[mi][2], af[mi][3],
                             bf[ni][0], bf[ni][1]);
            if (SPLIT) {
                uint32_t afl[4][4], bfl[4][2];
#pragma unroll
                for (int mi = 0; mi < 4; mi++) {
                    const int mr = wm + mi * 16 + r;
                    afl[mi][0] = __float_as_uint(As[TILE + mr * STR + kb]);
                    afl[mi][1] = __float_as_uint(As[TILE + (mr + 8) * STR + kb]);
                    afl[mi][2] = __float_as_uint(As[TILE + mr * STR + kb + 4]);
                    afl[mi][3] = __float_as_uint(As[TILE + (mr + 8) * STR + kb + 4]);
                }
#pragma unroll
                for (int ni = 0; ni < 4; ni++) {
                    const int nr = wn + ni * 8 + r;
                    bfl[ni][0] = __float_as_uint(Bs[TILE + nr * STR + kb]);
                    bfl[ni][1] = __float_as_uint(Bs[TILE + nr * STR + kb + 4]);
                }
#pragma unroll
                for (int mi = 0; mi < 4; mi++)
#pragma unroll
                    for (int ni = 0; ni < 4; ni++) {
                        mma_tf32(acc[mi][ni], af[mi][0], af[mi][1], af[mi][2], af[mi][3],
                                 bfl[ni][0], bfl[ni][1]);
                        mma_tf32(acc[mi][ni], afl[mi][0], afl[mi][1], afl[mi][2], afl[mi][3],
                                 bf[ni][0], bf[ni][1]);
                    }
            }
        }
        __syncthreads();
    }

    // ---- epilogue ----
#pragma unroll
    for (int mi = 0; mi < 4; mi++) {
#pragma unroll
        for (int ni = 0; ni < 4; ni++) {
            const int row = m0 + wm + mi * 16 + r;
            const int col = n0 + wn + ni * 8 + 2 * c;
#pragma unroll
            for (int t = 0; t < 4; t++) {
                const int rr2 = row + (t >= 2 ? 8 : 0);
                const int cc2 = col + (t & 1);
                if (cc2 < N) {
                    float v = acc[mi][ni][t];
                    if (bias) v += __ldg(bias + cc2);
                    if (EPI == 1) v = fmaxf(v, 0.f);
                    if (EPI == 2) v += pe[((rr2 & 511) << 9) + cc2];
                    C[(size_t)rr2 * N + cc2] = v;
                }
            }
        }
    }
}

// ---------------------------------------------------------------------------
// Fused flash attention: o = softmax(QK^T/8) @ V, per (b,h), no score tensor.
// grid (8 qtile, 256 bh), 128 threads (4 warps, each owns 16 q-rows x 64).
// Dynamic smem: Qs(64x68) Ks(64x68) Ps(64x68) Vs(64x72) = 70656 B.
// ---------------------------------------------------------------------------
__global__ void __launch_bounds__(128) flash_attn_tc(
    const float* __restrict__ qkv, float* __restrict__ o)
{
    extern __shared__ float sm[];
    constexpr int STR  = 68;
    constexpr int VSTR = 72;
    float* Qs = sm;                     // [m][d]    64*68
    float* Ks = Qs + 64 * STR;          // [n][d]    64*68
    float* Ps = Ks + 64 * STR;          // [m][kpos] 64*68
    float* Vs = Ps + 64 * STR;          // [kpos][d] 64*72

    const int qt = blockIdx.x, bh = blockIdx.y;
    const int b = bh >> 3, h = bh & 7;
    const int tid = threadIdx.x, lane = tid & 31, wid = tid >> 5;
    const int wm = wid * 16;
    const int r = lane >> 2, c = lane & 3;

    // ---- load Q tile 64x64 (tf32) ----
#pragma unroll
    for (int i = 0; i < 8; i++) {
        int idx = tid + i * 128;
        int kg = idx & 15, m = idx >> 4;
        float4 v = *reinterpret_cast<const float4*>(
            qkv + (size_t)(b * 512 + qt * 64 + m) * 1536 + h * 64 + kg * 4);
        float4 hv;
        hv.x = tf32_rna(v.x); hv.y = tf32_rna(v.y);
        hv.z = tf32_rna(v.z); hv.w = tf32_rna(v.w);
        *reinterpret_cast<float4*>(&Qs[m * STR + kg * 4]) = hv;
    }

    float m_r[2] = {-3.402823466e38f, -3.402823466e38f};
    float l_r[2] = {0.f, 0.f};
    float oacc[8][4];
#pragma unroll
    for (int nf = 0; nf < 8; nf++)
#pragma unroll
        for (int t = 0; t < 4; t++) oacc[nf][t] = 0.f;

    for (int kc = 0; kc < 8; kc++) {
        // ---- load K chunk [n][d] and V chunk [kpos][d] (tf32) ----
#pragma unroll
        for (int i = 0; i < 8; i++) {
            int idx = tid + i * 128;
            int kg = idx & 15, m = idx >> 4;
            const float* base = qkv + (size_t)(b * 512 + kc * 64 + m) * 1536 + h * 64 + kg * 4;
            float4 kv = *reinterpret_cast<const float4*>(base + 512);
            float4 hk;
            hk.x = tf32_rna(kv.x); hk.y = tf32_rna(kv.y);
            hk.z = tf32_rna(kv.z); hk.w = tf32_rna(kv.w);
            *reinterpret_cast<float4*>(&Ks[m * STR + kg * 4]) = hk;
            float4 vv = *reinterpret_cast<const float4*>(base + 1024);
            float4 hvv;
            hvv.x = tf32_rna(vv.x); hvv.y = tf32_rna(vv.y);
            hvv.z = tf32_rna(vv.z); hvv.w = tf32_rna(vv.w);
            *reinterpret_cast<float4*>(&Vs[m * VSTR + kg * 4]) = hvv;
        }
        __syncthreads();

        // ---- S = Q K^T (warp tile 16x64), contraction over d=64 ----
        float sacc[8][4];
#pragma unroll
        for (int nf = 0; nf < 8; nf++)
#pragma unroll
            for (int t = 0; t < 4; t++) sacc[nf][t] = 0.f;

#pragma unroll
        for (int ks = 0; ks < 8; ks++) {
            const int kb = ks * 8 + c;
            uint32_t a0 = __float_as_uint(Qs[(wm + r) * STR + kb]);
            uint32_t a1 = __float_as_uint(Qs[(wm + r + 8) * STR + kb]);
            uint32_t a2 = __float_as_uint(Qs[(wm + r) * STR + kb + 4]);
            uint32_t a3 = __float_as_uint(Qs[(wm + r + 8) * STR + kb + 4]);
#pragma unroll
            for (int nf = 0; nf < 8; nf++) {
                const int nr = nf * 8 + r;
                uint32_t b0 = __float_as_uint(Ks[nr * STR + kb]);
                uint32_t b1 = __float_as_uint(Ks[nr * STR + kb + 4]);
                mma_tf32(sacc[nf], a0, a1, a2, a3, b0, b1);
            }
        }

        // ---- scale, row-max (rows r and r+8 of warp tile) ----
        float mx0 = -3.402823466e38f, mx1 = -3.402823466e38f;
#pragma unroll
        for (int nf = 0; nf < 8; nf++) {
#pragma unroll
            for (int t = 0; t < 4; t++) sacc[nf][t] *= 0.125f;
            mx0 = fmaxf(mx0, fmaxf(sacc[nf][0], sacc[nf][1]));
            mx1 = fmaxf(mx1, fmaxf(sacc[nf][2], sacc[nf][3]));
        }
        mx0 = fmaxf(mx0, __shfl_xor_sync(0xffffffffu, mx0, 1));
        mx0 = fmaxf(mx0, __shfl_xor_sync(0xffffffffu, mx0, 2));
        mx1 = fmaxf(mx1, __shfl_xor_sync(0xffffffffu, mx1, 1));
        mx1 = fmaxf(mx1, __shfl_xor_sync(0xffffffffu, mx1, 2));

        const float mn0 = fmaxf(m_r[0], mx0);
        const float mn1 = fmaxf(m_r[1], mx1);
        const float f0 = expf(m_r[0] - mn0);
        const float f1 = expf(m_r[1] - mn1);

        // ---- P = exp(S - m), row-sum, store P (tf32) to smem ----
        float s0 = 0.f, s1 = 0.f;
#pragma unroll
        for (int nf = 0; nf < 8; nf++) {
            float p0 = expf(sacc[nf][0] - mn0);
            float p1 = expf(sacc[nf][1] - mn0);
            float p2 = expf(sacc[nf][2] - mn1);
            float p3 = expf(sacc[nf][3] - mn1);
            s0 += p0 + p1;
            s1 += p2 + p3;
            float2 q01 = make_float2(tf32_rna(p0), tf32_rna(p1));
            float2 q23 = make_float2(tf32_rna(p2), tf32_rna(p3));
            *reinterpret_cast<float2*>(&Ps[(wm + r) * STR + nf * 8 + 2 * c]) = q01;
            *reinterpret_cast<float2*>(&Ps[(wm + r + 8) * STR + nf * 8 + 2 * c]) = q23;
            // rescale running output
            oacc[nf][0] *= f0; oacc[nf][1] *= f0;
            oacc[nf][2] *= f1; oacc[nf][3] *= f1;
        }
        s0 += __shfl_xor_sync(0xffffffffu, s0, 1);
        s0 += __shfl_xor_sync(0xffffffffu, s0, 2);
        s1 += __shfl_xor_sync(0xffffffffu, s1, 1);
        s1 += __shfl_xor_sync(0xffffffffu, s1, 2);
        l_r[0] = l_r[0] * f0 + s0;
        l_r[1] = l_r[1] * f1 + s1;
        m_r[0] = mn0; m_r[1] = mn1;
        __syncwarp();

        // ---- O += P @ V, contraction over kpos=64 ----
#pragma unroll
        for (int ks = 0; ks < 8; ks++) {
            const int kb = ks * 8 + c;
            uint32_t a0 = __float_as_uint(Ps[(wm + r) * STR + kb]);
            uint32_t a1 = __float_as_uint(Ps[(wm + r + 8) * STR + kb]);
            uint32_t a2 = __float_as_uint(Ps[(wm + r) * STR + kb + 4]);
            uint32_t a3 = __float_as_uint(Ps[(wm + r + 8) * STR + kb + 4]);
#pragma unroll
            for (int nf = 0; nf < 8; nf++) {
                const int nr = nf * 8 + r;
                uint32_t b0 = __float_as_uint(Vs[kb * VSTR + nr]);
                uint32_t b1 = __float_as_uint(Vs[(kb + 4) * VSTR + nr]);
                mma_tf32(oacc[nf], a0, a1, a2, a3, b0, b1);
            }
        }
        __syncthreads();
    }

    // ---- epilogue: divide by l, write o[b, q, h*64+d] ----
    const float inv0 = 1.f / l_r[0];
    const float inv1 = 1.f / l_r[1];
#pragma unroll
    for (int nf = 0; nf < 8; nf++) {
        const int row = qt * 64 + wm + r;
        const int col = nf * 8 + 2 * c;
        float* ob = o + (size_t)(b * 512 + row) * 512 + h * 64 + col;
        ob[0]           = oacc[nf][0] * inv0;
        ob[1]           = oacc[nf][1] * inv0;
        ob[8 * 512]     = oacc[nf][2] * inv1;
        ob[8 * 512 + 1] = oacc[nf][3] * inv1;
    }
}

// ---------------------------------------------------------------------------
// Row softmax, row length = CPT*256, one block of 256 threads per row
// ---------------------------------------------------------------------------
template <int CPT>
__global__ void __launch_bounds__(256) softmax_kernel(float* __restrict__ data)
{
    float* row = data + (size_t)blockIdx.x * (CPT * 256);
    const int tid = threadIdx.x;
    float x[CPT];
    float mx = -3.402823466e38f;
#pragma unroll
    for (int c = 0; c < CPT; c++) {
        x[c] = row[tid + 256 * c];
        mx = fmaxf(mx, x[c]);
    }
    __shared__ float sh[8];
#pragma unroll
    for (int o = 16; o; o >>= 1) mx = fmaxf(mx, __shfl_xor_sync(0xffffffffu, mx, o));
    if ((tid & 31) == 0) sh[tid >> 5] = mx;
    __syncthreads();
    mx = sh[0];
#pragma unroll
    for (int w = 1; w < 8; w++) mx = fmaxf(mx, sh[w]);

    float s = 0.f;
#pragma unroll
    for (int c = 0; c < CPT; c++) { x[c] = expf(x[c] - mx); s += x[c]; }
    __syncthreads();
#pragma unroll
    for (int o = 16; o; o >>= 1) s += __shfl_xor_sync(0xffffffffu, s, o);
    if ((tid & 31) == 0) sh[tid >> 5] = s;
    __syncthreads();
    float tot = sh[0];
#pragma unroll
    for (int w = 1; w < 8; w++) tot += sh[w];
    float inv = 1.f / tot;
#pragma unroll
    for (int c = 0; c < CPT; c++) row[tid + 256 * c] = x[c] * inv;
}

// ---------------------------------------------------------------------------
// out = LayerNorm(X + Y) * g + b  (row length 512, one block per row)
// ---------------------------------------------------------------------------
__global__ void __launch_bounds__(256) add_ln_kernel(
    const float* __restrict__ X, const float* __restrict__ Y,
    const float* __restrict__ gam, const float* __restrict__ bet,
    float* __restrict__ out)
{
    const size_t row = blockIdx.x;
    const float* xr = X + row * 512;
    const float* yr = Y + row * 512;
    const int tid = threadIdx.x;
    float t0 = xr[tid] + yr[tid];
    float t1 = xr[tid + 256] + yr[tid + 256];

    __shared__ float sh[8];
    float s = t0 + t1;
#pragma unroll
    for (int o = 16; o; o >>= 1) s += __shfl_xor_sync(0xffffffffu, s, o);
    if ((tid & 31) == 0) sh[tid >> 5] = s;
    __syncthreads();
    float tot = sh[0];
#pragma unroll
    for (int w = 1; w < 8; w++) tot += sh[w];
    float mean = tot * (1.f / 512.f);
    float d0 = t0 - mean, d1 = t1 - mean;
    float q = d0 * d0 + d1 * d1;
    __syncthreads();
#pragma unroll
    for (int o = 16; o; o >>= 1) q += __shfl_xor_sync(0xffffffffu, q, o);
    if ((tid & 31) == 0) sh[tid >> 5] = q;
    __syncthreads();
    float vtot = sh[0];
#pragma unroll
    for (int w = 1; w < 8; w++) vtot += sh[w];
    float inv = rsqrtf(vtot * (1.f / 512.f) + 1e-5f);
    float* orow = out + row * 512;
    orow[tid] = d0 * inv * gam[tid] + bet[tid];
    orow[tid + 256] = d1 * inv * gam[tid + 256] + bet[tid + 256];
}

// ---------------------------------------------------------------------------
// Graph branch (exact fp32, tiny cost)
// ---------------------------------------------------------------------------
__global__ void feat_fn_kernel(const float* __restrict__ x, float* __restrict__ fn)
{
    const int b = blockIdx.x, i = threadIdx.x; // 64 threads
    const float* xp = x + (size_t)b * 32768 + i;
    float s = 0.f;
    for (int t = 0; t < 512; t++) s += xp[(size_t)t * 64];
    float f = s * (1.f / 512.f);
    __shared__ float sh[64];
    sh[i] = f * f;
    __syncthreads();
    for (int o = 32; o; o >>= 1) {
        if (i < o) sh[i] += sh[i + o];
        __syncthreads();
    }
    float norm = sqrtf(sh[0]);
    fn[b * 64 + i] = f / fmaxf(norm, 1e-12f);
}

__global__ void graph_adj_kernel(const float* __restrict__ fn, float* __restrict__ An)
{
    const int b = blockIdx.x, i = threadIdx.x; // 64 threads
    __shared__ float f[64];
    __shared__ unsigned char A[64][64];
    f[i] = fn[b * 64 + i];
    for (int j = 0; j < 64; j++) A[i][j] = 0;
    __syncthreads();
    const float fi = f[i];
    float bv0 = -3.402823466e38f, bv1 = bv0, bv2 = bv0, bv3 = bv0;
    int i0 = 0, i1 = 0, i2 = 0, i3 = 0;
    for (int j = 0; j < 64; j++) {
        float v = fi * f[j];
        if (v > bv3) {
            if (v > bv0)      { bv3 = bv2; i3 = i2; bv2 = bv1; i2 = i1; bv1 = bv0; i1 = i0; bv0 = v; i0 = j; }
            else if (v > bv1) { bv3 = bv2; i3 = i2; bv2 = bv1; i2 = i1; bv1 = v; i1 = j; }
            else if (v > bv2) { bv3 = bv2; i3 = i2; bv2 = v; i2 = j; }
            else              { bv3 = v; i3 = j; }
        }
    }
    A[i][i1] = 1; A[i][i2] = 1; A[i][i3] = 1;
    __syncthreads();
    float deg = 0.f;
    for (int j = 0; j < 64; j++) {
        bool a = (j == i) || A[i][j] || A[j][i];
        deg += a ? 1.f : 0.f;
    }
    float inv = 1.f / deg;
    float* row = An + (size_t)b * 4096 + i * 64;
    for (int j = 0; j < 64; j++) {
        bool a = (j == i) || A[i][j] || A[j][i];
        row[j] = a ? inv : 0.f;
    }
}

// t1[b,f,d] = sum_s x[b,s,f] * w[d,s] + bias[d]   (M=64 f, N=512 d, K=512 s)
__global__ void __launch_bounds__(256) gcn_gemm1_kernel(
    const float* __restrict__ x, const float* __restrict__ w,
    const float* __restrict__ bias, float* __restrict__ out)
{
    const int dt = blockIdx.x, b = blockIdx.y;
    __shared__ float Xs[16][64];
    __shared__ float Ws[64][17];
    const int tid = threadIdx.x, tx = tid & 15, ty = tid >> 4;
    float acc[4][4];
#pragma unroll
    for (int i = 0; i < 4; i++)
#pragma unroll
        for (int j = 0; j < 4; j++) acc[i][j] = 0.f;

    for (int k0 = 0; k0 < 512; k0 += 16) {
        {
            int kk = tid >> 4, f4 = (tid & 15) << 2;
            float4 v = *reinterpret_cast<const float4*>(
                x + (size_t)b * 32768 + (size_t)(k0 + kk) * 64 + f4);
            *reinterpret_cast<float4*>(&Xs[kk][f4]) = v;
            int dd = tid >> 2, k4 = (tid & 3) << 2;
            float4 w4 = *reinterpret_cast<const float4*>(
                w + (size_t)(dt * 64 + dd) * 512 + k0 + k4);
            Ws[dd][k4 + 0] = w4.x; Ws[dd][k4 + 1] = w4.y;
            Ws[dd][k4 + 2] = w4.z; Ws[dd][k4 + 3] = w4.w;
        }
        __syncthreads();
#pragma unroll
        for (int kk = 0; kk < 16; kk++) {
            float a[4], bb[4];
#pragma unroll
            for (int i = 0; i < 4; i++) a[i] = Xs[kk][ty + 16 * i];
#pragma unroll
            for (int j = 0; j < 4; j++) bb[j] = Ws[tx + 16 * j][kk];
#pragma unroll
            for (int i = 0; i < 4; i++)
#pragma unroll
                for (int j = 0; j < 4; j++)
                    acc[i][j] = fmaf(a[i], bb[j], acc[i][j]);
        }
        __syncthreads();
    }
#pragma unroll
    for (int i = 0; i < 4; i++)
#pragma unroll
        for (int j = 0; j < 4; j++) {
            int dd = dt * 64 + tx + 16 * j;
            out[(size_t)b * 32768 + (size_t)(ty + 16 * i) * 512 + dd] =
                acc[i][j] + bias[dd];
        }
}

// t2[b,f,s] = sum_d Ain[b,f,d] * w[s,d] + bias[s]
__global__ void __launch_bounds__(256) gcn_gemm2_kernel(
    const float* __restrict__ Ain, const float* __restrict__ w,
    const float* __restrict__ bias, float* __restrict__ out)
{
    const int st = blockIdx.x, b = blockIdx.y;
    __shared__ float As[64][17];
    __shared__ float Ws[64][17];
    const int tid = threadIdx.x, tx = tid & 15, ty = tid >> 4;
    const int rr = tid >> 2, k4 = (tid & 3) << 2;
    float acc[4][4];
#pragma unroll
    for (int i = 0; i < 4; i++)
#pragma unroll
        for (int j = 0; j < 4; j++) acc[i][j] = 0.f;

    for (int k0 = 0; k0 < 512; k0 += 16) {
        float4 a4 = *reinterpret_cast<const float4*>(
            Ain + (size_t)b * 32768 + (size_t)rr * 512 + k0 + k4);
        As[rr][k4 + 0] = a4.x; As[rr][k4 + 1] = a4.y;
        As[rr][k4 + 2] = a4.z; As[rr][k4 + 3] = a4.w;
        float4 w4 = *reinterpret_cast<const float4*>(
            w + (size_t)(st * 64 + rr) * 512 + k0 + k4);
        Ws[rr][k4 + 0] = w4.x; Ws[rr][k4 + 1] = w4.y;
        Ws[rr][k4 + 2] = w4.z; Ws[rr][k4 + 3] = w4.w;
        __syncthreads();
#pragma unroll
        for (int kk = 0; kk < 16; kk++) {
            float a[4], bb[4];
#pragma unroll
            for (int i = 0; i < 4; i++) a[i] = As[ty + 16 * i][kk];
#pragma unroll
            for (int j = 0; j < 4; j++) bb[j] = Ws[tx + 16 * j][kk];
#pragma unroll
            for (int i = 0; i < 4; i++)
#pragma unroll
                for (int j = 0; j < 4; j++)
                    acc[i][j] = fmaf(a[i], bb[j], acc[i][j]);
        }
        __syncthreads();
    }
#pragma unroll
    for (int i = 0; i < 4; i++)
#pragma unroll
        for (int j = 0; j < 4; j++) {
            int ss = st * 64 + tx + 16 * j;
            out[(size_t)b * 32768 + (size_t)(ty + 16 * i) * 512 + ss] =
                acc[i][j] + bias[ss];
        }
}

// out = (relu?) An @ in ; optional transposed write g_out[b, s, f]
template <bool RELU, bool TRANSOUT>
__global__ void __launch_bounds__(256) an_mult_kernel(
    const float* __restrict__ An, const float* __restrict__ in,
    float* __restrict__ out)
{
    const int dt = blockIdx.x, b = blockIdx.y;
    __shared__ float As[64][65];
    __shared__ float Ins[64][64];
    const int tid = threadIdx.x, tx = tid & 15, ty = tid >> 4;

    for (int t = tid; t < 4096; t += 256)
        As[t >> 6][t & 63] = An[(size_t)b * 4096 + t];
#pragma unroll
    for (int hh = 0; hh < 4; hh++) {
        int idx4 = tid + hh * 256;
        int gg = idx4 >> 4, c4 = (idx4 & 15) << 2;
        float4 v = *reinterpret_cast<const float4*>(
            in + (size_t)b * 32768 + (size_t)gg * 512 + dt * 64 + c4);
        *reinterpret_cast<float4*>(&Ins[gg][c4]) = v;
    }
    __syncthreads();

    float acc[4][4];
#pragma unroll
    for (int i = 0; i < 4; i++)
#pragma unroll
        for (int j = 0; j < 4; j++) acc[i][j] = 0.f;

#pragma unroll 8
    for (int kk = 0; kk < 64; kk++) {
        float a[4], bb[4];
#pragma unroll
        for (int i = 0; i < 4; i++) a[i] = As[ty + 16 * i][kk];
#pragma unroll
        for (int j = 0; j < 4; j++) bb[j] = Ins[kk][tx + 16 * j];
#pragma unroll
        for (int i = 0; i < 4; i++)
#pragma unroll
            for (int j = 0; j < 4; j++)
                acc[i][j] = fmaf(a[i], bb[j], acc[i][j]);
    }

#pragma unroll
    for (int i = 0; i < 4; i++)
#pragma unroll
        for (int j = 0; j < 4; j++) {
            int ff = ty + 16 * i;
            int dd = dt * 64 + tx + 16 * j;
            float v = acc[i][j];
            if (RELU) v = fmaxf(v, 0.f);
            if (!TRANSOUT)
                out[(size_t)b * 32768 + (size_t)ff * 512 + dd] = v;
            else
                out[(size_t)b * 32768 + (size_t)dd * 64 + ff] = v;
        }
}

// ---------------------------------------------------------------------------
// Host orchestration
// ---------------------------------------------------------------------------
extern "C" void kernel_launch(void* const* d_in, const int* in_sizes, int n_in,
                              void* d_out, int out_size)
{
    const float* x      = (const float*)d_in[0];
    const float* W_in   = (const float*)d_in[1];
    const float* b_in   = (const float*)d_in[2];
    const float* qkv_w  = (const float*)d_in[3];
    const float* qkv_b  = (const float*)d_in[4];
    const float* out_w  = (const float*)d_in[5];
    const float* out_b  = (const float*)d_in[6];
    const float* ln1_g  = (const float*)d_in[7];
    const float* ln1_b  = (const float*)d_in[8];
    const float* ln2_g  = (const float*)d_in[9];
    const float* ln2_b  = (const float*)d_in[10];
    const float* ff1_w  = (const float*)d_in[11];
    const float* ff1_b  = (const float*)d_in[12];
    const float* ff2_w  = (const float*)d_in[13];
    const float* ff2_b  = (const float*)d_in[14];
    const float* memory = (const float*)d_in[15];
    const float* fc1_w  = (const float*)d_in[16];
    const float* fc1_b  = (const float*)d_in[17];
    const float* fc2_w  = (const float*)d_in[18];
    const float* fc2_b  = (const float*)d_in[19];
    const float* gc1_w  = (const float*)d_in[20];
    const float* gc1_b  = (const float*)d_in[21];
    const float* gc2_w  = (const float*)d_in[22];
    const float* gc2_b  = (const float*)d_in[23];

    float* out    = (float*)d_out;
    float* t_out  = out;                       // (32,512,64)
    float* gout_p = out + 1048576;             // (32,512,64)
    float* attn_p = out + 2097152;             // (32,512,1024)

    const int FA_SMEM = (3 * 68 + 72) * 64 * 4;   // 70656 bytes

    static float *p_pe = nullptr, *p_h, *p_tmp, *p_qkv, *p_o, *p_ff,
                 *p_upd, *p_t1, *p_fn, *p_An, *p_gt1, *p_gh1;
    if (!p_pe) {
        cudaGetSymbolAddress((void**)&p_pe,  g_pe);
        cudaGetSymbolAddress((void**)&p_h,   g_h);
        cudaGetSymbolAddress((void**)&p_tmp, g_tmp);
        cudaGetSymbolAddress((void**)&p_qkv, g_qkv);
        cudaGetSymbolAddress((void**)&p_o,   g_o);
        cudaGetSymbolAddress((void**)&p_ff,  g_ff);
        cudaGetSymbolAddress((void**)&p_upd, g_upd);
        cudaGetSymbolAddress((void**)&p_t1,  g_t1);
        cudaGetSymbolAddress((void**)&p_fn,  g_fn);
        cudaGetSymbolAddress((void**)&p_An,  g_An);
        cudaGetSymbolAddress((void**)&p_gt1, g_gt1);
        cudaGetSymbolAddress((void**)&p_gh1, g_gh1);
        cudaFuncSetAttribute(flash_attn_tc,
                             cudaFuncAttributeMaxDynamicSharedMemorySize, FA_SMEM);
    }

    const int M = 16384;

    // positional encoding
    pe_kernel<<<(512 * 512 + 255) / 256, 256>>>(p_pe);

    // h = x @ W_in^T + b_in + pe
    gemm_tc<true, 2, false><<<dim3(4, 128), 256>>>(
        x, nullptr, W_in, b_in, p_pe, p_h, M, 512, 64);

    for (int l = 0; l < 3; l++) {
        // qkv
        gemm_tc<true, 0, false><<<dim3(12, 128), 256>>>(
            p_h, nullptr, qkv_w + (size_t)l * 1536 * 512, qkv_b + l * 1536, nullptr,
            p_qkv, M, 1536, 512);
        // fused attention (scores + softmax + att@v, no materialized scores)
        flash_attn_tc<<<dim3(8, 256), 128, FA_SMEM>>>(p_qkv, p_o);
        // out projection
        gemm_tc<true, 0, false><<<dim3(4, 128), 256>>>(
            p_o, nullptr, out_w + (size_t)l * 512 * 512, out_b + l * 512, nullptr,
            p_tmp, M, 512, 512);
        add_ln_kernel<<<16384, 256>>>(p_h, p_tmp, ln1_g + l * 512, ln1_b + l * 512, p_h);
        // feed-forward
        gemm_tc<true, 1, false><<<dim3(16, 128), 256>>>(
            p_h, nullptr, ff1_w + (size_t)l * 2048 * 512, ff1_b + l * 2048, nullptr,
            p_ff, M, 2048, 512);
        gemm_tc<true, 0, false><<<dim3(4, 128), 256>>>(
            p_ff, nullptr, ff2_w + (size_t)l * 512 * 2048, ff2_b + l * 512, nullptr,
            p_tmp, M, 512, 2048);
        add_ln_kernel<<<16384, 256>>>(p_h, p_tmp, ln2_g + l * 512, ln2_b + l * 512, p_h);
    }

    // memory attention: sims (3xTF32 for accuracy) -> softmax -> upd
    gemm_tc<true, 0, true><<<dim3(8, 128), 256>>>(
        p_h, nullptr, memory, nullptr, nullptr, attn_p, M, 1024, 512);
    softmax_kernel<4><<<16384, 256>>>(attn_p);
    gemm_tc<false, 0, false><<<dim3(4, 128), 256>>>(
        attn_p, nullptr, memory, nullptr, nullptr, p_upd, M, 512, 1024);
    // fc1 over virtual concat [h | upd] (CATAB), then fc2
    gemm_tc<true, 1, false, true><<<dim3(4, 128), 256>>>(
        p_h, p_upd, fc1_w, fc1_b, nullptr, p_t1, M, 512, 1024);
    gemm_tc<true, 0, false><<<dim3(1, 128), 256>>>(
        p_t1, nullptr, fc2_w, fc2_b, nullptr, t_out, M, 64, 512);

    // graph branch (exact fp32)
    feat_fn_kernel<<<32, 64>>>(x, p_fn);
    graph_adj_kernel<<<32, 64>>>(p_fn, p_An);
    gcn_gemm1_kernel<<<dim3(8, 32), 256>>>(x, gc1_w, gc1_b, p_gt1);
    an_mult_kernel<true, false><<<dim3(8, 32), 256>>>(p_An, p_gt1, p_gh1);
    gcn_gemm2_kernel<<<dim3(8, 32), 256>>>(p_gh1, gc2_w, gc2_b, p_gt1);
    an_mult_kernel<false, true><<<dim3(8, 32), 256>>>(p_An, p_gt1, gout_p);

    (void)in_sizes; (void)n_in; (void)out_size;
}

// round 7
// speedup vs baseline: 4.1395x; 1.3311x over previous
#include <cuda_runtime.h>
#include <cuda_fp16.h>
#include <math.h>
#include <stdint.h>

// ---------------------------------------------------------------------------
// Problem constants
//  B=32, S=512, F_IN=64, D=512, DFF=2048, MEM=1024, L=3, H=8, dh=64
//  rows = B*S = 16384
// ---------------------------------------------------------------------------

// ------------------------- static scratch buffers --------------------------
__device__ float g_pe[512 * 512];            // 1 MB
__device__ float g_h[16384 * 512];           // 32 MB
__device__ float g_tmp[16384 * 512];         // 32 MB
__device__ float g_qkv[16384 * 1536];        // 96 MB
__device__ float g_o[16384 * 512];           // 32 MB
__device__ float g_ff[16384 * 2048];         // 128 MB
__device__ float g_upd[16384 * 512];         // 32 MB
__device__ float g_t1[16384 * 512];          // 32 MB
__device__ float g_fn[32 * 64];
__device__ float g_An[32 * 64 * 64];
__device__ float g_gt1[32 * 64 * 512];       // 4 MB
__device__ float g_gh1[32 * 64 * 512];       // 4 MB

// ---------------------------------------------------------------------------
// fp16 helpers
// ---------------------------------------------------------------------------
__device__ __forceinline__ uint32_t pack_half2(float a, float b) {
    __half2 h = __floats2half2_rn(a, b);
    return *reinterpret_cast<uint32_t*>(&h);
}

__device__ __forceinline__ void mma_f16(float c[4],
    uint32_t a0, uint32_t a1, uint32_t a2, uint32_t a3,
    uint32_t b0, uint32_t b1)
{
    asm volatile(
        "mma.sync.aligned.m16n8k16.row.col.f32.f16.f16.f32 "
        "{%0,%1,%2,%3}, {%4,%5,%6,%7}, {%8,%9}, {%0,%1,%2,%3};"
        : "+f"(c[0]), "+f"(c[1]), "+f"(c[2]), "+f"(c[3])
        : "r"(a0), "r"(a1), "r"(a2), "r"(a3), "r"(b0), "r"(b1));
}

// ---------------------------------------------------------------------------
// Positional encoding (match numpy float64 -> float32)
// ---------------------------------------------------------------------------
__global__ void pe_kernel(float* __restrict__ pe) {
    int i = blockIdx.x * 256 + threadIdx.x;
    if (i >= 512 * 512) return;
    int s = i >> 9, d = i & 511;
    int t2 = d & ~1;
    double div = exp((double)t2 * (-9.210340371976184 / 512.0)); // ln(10000)
    double a = (double)s * div;
    pe[i] = (float)((d & 1) ? cos(a) : sin(a));
}

// ---------------------------------------------------------------------------
// Tensor-core GEMM (fp16 mma, fp32 accumulate), register-staged pipeline.
//  C[M,N] = A[M,K] * op(B) + bias (+relu / +pe)
//   TRANSB=true : B is (N,K) row-major  -> C = A @ B^T
//   TRANSB=false: B is (K,N) row-major  -> C = A @ B
//   SPLIT=true  : 3-pass hi/lo fp16 split for higher accuracy
//   CATAB=true  : A is logical [M, 1024] = concat(A[:,0:512], A2[:,0:512])
// Block tile 128x128, 256 threads (8 warps = 2m x 4n of 64x32 warp tiles).
// KT=32 fp16 elements per K-tile (two k16 mma steps).
// EPI: 0 = bias, 1 = bias+relu, 2 = bias + positional encoding add
// ---------------------------------------------------------------------------
template <bool TRANSB, int EPI, bool SPLIT, bool CATAB = false>
__global__ void __launch_bounds__(256) gemm_tc(
    const float* __restrict__ A, const float* __restrict__ A2,
    const float* __restrict__ B,
    const float* __restrict__ bias, const float* __restrict__ pe,
    float* __restrict__ C, int M, int N, int K)
{
    constexpr int KT    = 32;              // fp16 elems per tile
    constexpr int STR2  = 20;              // half2 (uint) stride: 16 + 4
    constexpr int TILE2 = 128 * STR2;

    __shared__ uint32_t As[(SPLIT ? 2 : 1) * TILE2];
    __shared__ uint32_t Bs[(SPLIT ? 2 : 1) * TILE2];

    const int tid  = threadIdx.x;
    const int lane = tid & 31, wid = tid >> 5;
    const int wm = (wid >> 2) * 64, wn = (wid & 3) * 32;
    const int g = lane >> 2, c = lane & 3;
    const int m0 = blockIdx.y * 128, n0 = blockIdx.x * 128;

    float4 rA[4], rB[4];

    auto load_regs = [&](int k0) {
#pragma unroll
        for (int i = 0; i < 4; i++) {
            int idx = tid + i * 256;
            int kg = idx & 7, m = idx >> 3;       // 8 float4 per 32-float row
            const float* Ap = A;
            int lda = K, kcol = k0 + kg * 4;
            if (CATAB) {
                lda = 512;
                if (k0 >= 512) { Ap = A2; kcol -= 512; }
            }
            rA[i] = *reinterpret_cast<const float4*>(
                Ap + (size_t)(m0 + m) * lda + kcol);
        }
        if (TRANSB) {
#pragma unroll
            for (int i = 0; i < 4; i++) {
                int idx = tid + i * 256;
                int kg = idx & 7, n = idx >> 3;
                rB[i] = make_float4(0.f, 0.f, 0.f, 0.f);
                if (n0 + n < N)
                    rB[i] = *reinterpret_cast<const float4*>(
                        B + (size_t)(n0 + n) * K + k0 + kg * 4);
            }
        } else {
#pragma unroll
            for (int i = 0; i < 4; i++) {
                int idx = tid + i * 256;
                int ng = idx & 31, kk = idx >> 5;  // kk < 32
                int n = ng * 4;
                rB[i] = make_float4(0.f, 0.f, 0.f, 0.f);
                if (n0 + n < N)
                    rB[i] = *reinterpret_cast<const float4*>(
                        B + (size_t)(k0 + kk) * N + n0 + n);
            }
        }
    };

    auto store_smem = [&]() {
#pragma unroll
        for (int i = 0; i < 4; i++) {
            int idx = tid + i * 256;
            int kg = idx & 7, m = idx >> 3;
            float4 v = rA[i];
            uint2 hu;
            hu.x = pack_half2(v.x, v.y);
            hu.y = pack_half2(v.z, v.w);
            *reinterpret_cast<uint2*>(&As[m * STR2 + kg * 2]) = hu;
            if (SPLIT) {
                __half2 h2x = *reinterpret_cast<__half2*>(&hu.x);
                __half2 h2y = *reinterpret_cast<__half2*>(&hu.y);
                uint2 lu;
                lu.x = pack_half2(v.x - __low2float(h2x),  v.y - __high2float(h2x));
                lu.y = pack_half2(v.z - __low2float(h2y),  v.w - __high2float(h2y));
                *reinterpret_cast<uint2*>(&As[TILE2 + m * STR2 + kg * 2]) = lu;
            }
        }
        if (TRANSB) {
#pragma unroll
            for (int i = 0; i < 4; i++) {
                int idx = tid + i * 256;
                int kg = idx & 7, n = idx >> 3;
                float4 v = rB[i];
                uint2 hu;
                hu.x = pack_half2(v.x, v.y);
                hu.y = pack_half2(v.z, v.w);
                *reinterpret_cast<uint2*>(&Bs[n * STR2 + kg * 2]) = hu;
                if (SPLIT) {
                    __half2 h2x = *reinterpret_cast<__half2*>(&hu.x);
                    __half2 h2y = *reinterpret_cast<__half2*>(&hu.y);
                    uint2 lu;
                    lu.x = pack_half2(v.x - __low2float(h2x), v.y - __high2float(h2x));
                    lu.y = pack_half2(v.z - __low2float(h2y), v.w - __high2float(h2y));
                    *reinterpret_cast<uint2*>(&Bs[TILE2 + n * STR2 + kg * 2]) = lu;
                }
            }
        } else {
            __half* Bsh  = reinterpret_cast<__half*>(Bs);
#pragma unroll
            for (int i = 0; i < 4; i++) {
                int idx = tid + i * 256;
                int ng = idx & 31, kk = idx >> 5;
                int n = ng * 4;
                float4 v = rB[i];
                float vv[4] = {v.x, v.y, v.z, v.w};
#pragma unroll
                for (int j = 0; j < 4; j++) {
                    __half h = __float2half_rn(vv[j]);
                    Bsh[(n + j) * (STR2 * 2) + kk] = h;
                    if (SPLIT)
                        Bsh[2 * TILE2 + (n + j) * (STR2 * 2) + kk] =
                            __float2half_rn(vv[j] - __half2float(h));
                }
            }
        }
    };

    float acc[4][4][4];
#pragma unroll
    for (int i = 0; i < 4; i++)
#pragma unroll
        for (int j = 0; j < 4; j++)
#pragma unroll
            for (int t = 0; t < 4; t++) acc[i][j][t] = 0.f;

    load_regs(0);

    for (int k0 = 0; k0 < K; k0 += KT) {
        store_smem();
        __syncthreads();
        if (k0 + KT < K) load_regs(k0 + KT);   // overlap with MMA below

#pragma unroll
        for (int ks = 0; ks < 2; ks++) {       // two k16 steps
            const int kb = ks * 8 + c;
            uint32_t af[4][4], bf[4][2];
#pragma unroll
            for (int mi = 0; mi < 4; mi++) {
                const int mr = wm + mi * 16 + g;
                af[mi][0] = As[mr * STR2 + kb];
                af[mi][1] = As[(mr + 8) * STR2 + kb];
                af[mi][2] = As[mr * STR2 + kb + 4];
                af[mi][3] = As[(mr + 8) * STR2 + kb + 4];
            }
#pragma unroll
            for (int ni = 0; ni < 4; ni++) {
                const int nr = wn + ni * 8 + g;
                bf[ni][0] = Bs[nr * STR2 + kb];
                bf[ni][1] = Bs[nr * STR2 + kb + 4];
            }
#pragma unroll
            for (int mi = 0; mi < 4; mi++)
#pragma unroll
                for (int ni = 0; ni < 4; ni++)
                    mma_f16(acc[mi][ni], af[mi][0], af[mi][1], af[mi][2], af[mi][3],
                            bf[ni][0], bf[ni][1]);
            if (SPLIT) {
                uint32_t afl[4][4], bfl[4][2];
#pragma unroll
                for (int mi = 0; mi < 4; mi++) {
                    const int mr = wm + mi * 16 + g;
                    afl[mi][0] = As[TILE2 + mr * STR2 + kb];
                    afl[mi][1] = As[TILE2 + (mr + 8) * STR2 + kb];
                    afl[mi][2] = As[TILE2 + mr * STR2 + kb + 4];
                    afl[mi][3] = As[TILE2 + (mr + 8) * STR2 + kb + 4];
                }
#pragma unroll
                for (int ni = 0; ni < 4; ni++) {
                    const int nr = wn + ni * 8 + g;
                    bfl[ni][0] = Bs[TILE2 + nr * STR2 + kb];
                    bfl[ni][1] = Bs[TILE2 + nr * STR2 + kb + 4];
                }
#pragma unroll
                for (int mi = 0; mi < 4; mi++)
#pragma unroll
                    for (int ni = 0; ni < 4; ni++) {
                        mma_f16(acc[mi][ni], af[mi][0], af[mi][1], af[mi][2], af[mi][3],
                                bfl[ni][0], bfl[ni][1]);
                        mma_f16(acc[mi][ni], afl[mi][0], afl[mi][1], afl[mi][2], afl[mi][3],
                                bf[ni][0], bf[ni][1]);
                    }
            }
        }
        __syncthreads();
    }

    // ---- epilogue ----
#pragma unroll
    for (int mi = 0; mi < 4; mi++) {
#pragma unroll
        for (int ni = 0; ni < 4; ni++) {
            const int row = m0 + wm + mi * 16 + g;
            const int col = n0 + wn + ni * 8 + 2 * c;
#pragma unroll
            for (int t = 0; t < 4; t++) {
                const int rr2 = row + (t >= 2 ? 8 : 0);
                const int cc2 = col + (t & 1);
                if (cc2 < N) {
                    float v = acc[mi][ni][t];
                    if (bias) v += __ldg(bias + cc2);
                    if (EPI == 1) v = fmaxf(v, 0.f);
                    if (EPI == 2) v += pe[((rr2 & 511) << 9) + cc2];
                    C[(size_t)rr2 * N + cc2] = v;
                }
            }
        }
    }
}

// ---------------------------------------------------------------------------
// Fused flash attention (fp16 mma): o = softmax(QK^T/8) @ V per (b,h).
// grid (8 qtile, 256 bh), 128 threads (4 warps, each owns 16 q-rows).
// Static smem: Qs/Ks/Ps 64x36 uint (9216B each) + Vs 64x76 half (9728B).
// ---------------------------------------------------------------------------
__global__ void __launch_bounds__(128) flash_attn_tc(
    const float* __restrict__ qkv, float* __restrict__ o)
{
    constexpr int QSTR = 36;    // uint (half2) stride: 32 + 4
    constexpr int VSTR = 38;    // uint stride for V (76 halves)
    __shared__ uint32_t Qs[64 * QSTR];
    __shared__ uint32_t Ks[64 * QSTR];
    __shared__ uint32_t Ps[64 * QSTR];
    __shared__ uint32_t Vs[64 * VSTR];

    const int qt = blockIdx.x, bh = blockIdx.y;
    const int b = bh >> 3, h = bh & 7;
    const int tid = threadIdx.x, lane = tid & 31, wid = tid >> 5;
    const int wm = wid * 16;
    const int g = lane >> 2, c = lane & 3;

    // ---- load Q tile 64x64 (fp16) ----
#pragma unroll
    for (int i = 0; i < 8; i++) {
        int idx = tid + i * 128;
        int kg = idx & 15, m = idx >> 4;
        float4 v = *reinterpret_cast<const float4*>(
            qkv + (size_t)(b * 512 + qt * 64 + m) * 1536 + h * 64 + kg * 4);
        uint2 u;
        u.x = pack_half2(v.x, v.y);
        u.y = pack_half2(v.z, v.w);
        *reinterpret_cast<uint2*>(&Qs[m * QSTR + kg * 2]) = u;
    }

    float m_r[2] = {-3.402823466e38f, -3.402823466e38f};
    float l_r[2] = {0.f, 0.f};
    float oacc[8][4];
#pragma unroll
    for (int nf = 0; nf < 8; nf++)
#pragma unroll
        for (int t = 0; t < 4; t++) oacc[nf][t] = 0.f;

    __half* Vsh = reinterpret_cast<__half*>(Vs);

    for (int kc = 0; kc < 8; kc++) {
        // ---- load K chunk [n][d] and V chunk transposed [d][k] (fp16) ----
#pragma unroll
        for (int i = 0; i < 8; i++) {
            int idx = tid + i * 128;
            int kg = idx & 15, m = idx >> 4;
            const float* base = qkv + (size_t)(b * 512 + kc * 64 + m) * 1536 + h * 64 + kg * 4;
            float4 kv = *reinterpret_cast<const float4*>(base + 512);
            uint2 u;
            u.x = pack_half2(kv.x, kv.y);
            u.y = pack_half2(kv.z, kv.w);
            *reinterpret_cast<uint2*>(&Ks[m * QSTR + kg * 2]) = u;
            float4 vv = *reinterpret_cast<const float4*>(base + 1024);
            Vsh[(4 * kg + 0) * 76 + m] = __float2half_rn(vv.x);
            Vsh[(4 * kg + 1) * 76 + m] = __float2half_rn(vv.y);
            Vsh[(4 * kg + 2) * 76 + m] = __float2half_rn(vv.z);
            Vsh[(4 * kg + 3) * 76 + m] = __float2half_rn(vv.w);
        }
        __syncthreads();

        // ---- S = Q K^T (warp tile 16x64), contraction over d=64 ----
        float sacc[8][4];
#pragma unroll
        for (int nf = 0; nf < 8; nf++)
#pragma unroll
            for (int t = 0; t < 4; t++) sacc[nf][t] = 0.f;

#pragma unroll
        for (int ks = 0; ks < 4; ks++) {
            const int kb = ks * 8 + c;
            uint32_t a0 = Qs[(wm + g) * QSTR + kb];
            uint32_t a1 = Qs[(wm + g + 8) * QSTR + kb];
            uint32_t a2 = Qs[(wm + g) * QSTR + kb + 4];
            uint32_t a3 = Qs[(wm + g + 8) * QSTR + kb + 4];
#pragma unroll
            for (int nf = 0; nf < 8; nf++) {
                const int nr = nf * 8 + g;
                mma_f16(sacc[nf], a0, a1, a2, a3,
                        Ks[nr * QSTR + kb], Ks[nr * QSTR + kb + 4]);
            }
        }

        // ---- scale, row-max (rows g and g+8 of warp tile) ----
        float mx0 = -3.402823466e38f, mx1 = -3.402823466e38f;
#pragma unroll
        for (int nf = 0; nf < 8; nf++) {
#pragma unroll
            for (int t = 0; t < 4; t++) sacc[nf][t] *= 0.125f;
            mx0 = fmaxf(mx0, fmaxf(sacc[nf][0], sacc[nf][1]));
            mx1 = fmaxf(mx1, fmaxf(sacc[nf][2], sacc[nf][3]));
        }
        mx0 = fmaxf(mx0, __shfl_xor_sync(0xffffffffu, mx0, 1));
        mx0 = fmaxf(mx0, __shfl_xor_sync(0xffffffffu, mx0, 2));
        mx1 = fmaxf(mx1, __shfl_xor_sync(0xffffffffu, mx1, 1));
        mx1 = fmaxf(mx1, __shfl_xor_sync(0xffffffffu, mx1, 2));

        const float mn0 = fmaxf(m_r[0], mx0);
        const float mn1 = fmaxf(m_r[1], mx1);
        const float f0 = expf(m_r[0] - mn0);
        const float f1 = expf(m_r[1] - mn1);

        // ---- P = exp(S - m), row-sum, store P (fp16) to smem ----
        float s0 = 0.f, s1 = 0.f;
#pragma unroll
        for (int nf = 0; nf < 8; nf++) {
            float p0 = expf(sacc[nf][0] - mn0);
            float p1 = expf(sacc[nf][1] - mn0);
            float p2 = expf(sacc[nf][2] - mn1);
            float p3 = expf(sacc[nf][3] - mn1);
            s0 += p0 + p1;
            s1 += p2 + p3;
            Ps[(wm + g) * QSTR + nf * 4 + c]     = pack_half2(p0, p1);
            Ps[(wm + g + 8) * QSTR + nf * 4 + c] = pack_half2(p2, p3);
            oacc[nf][0] *= f0; oacc[nf][1] *= f0;
            oacc[nf][2] *= f1; oacc[nf][3] *= f1;
        }
        s0 += __shfl_xor_sync(0xffffffffu, s0, 1);
        s0 += __shfl_xor_sync(0xffffffffu, s0, 2);
        s1 += __shfl_xor_sync(0xffffffffu, s1, 1);
        s1 += __shfl_xor_sync(0xffffffffu, s1, 2);
        l_r[0] = l_r[0] * f0 + s0;
        l_r[1] = l_r[1] * f1 + s1;
        m_r[0] = mn0; m_r[1] = mn1;
        __syncwarp();

        // ---- O += P @ V, contraction over kpos=64 ----
#pragma unroll
        for (int ks = 0; ks < 4; ks++) {
            const int kb = ks * 8 + c;
            uint32_t a0 = Ps[(wm + g) * QSTR + kb];
            uint32_t a1 = Ps[(wm + g + 8) * QSTR + kb];
            uint32_t a2 = Ps[(wm + g) * QSTR + kb + 4];
            uint32_t a3 = Ps[(wm + g + 8) * QSTR + kb + 4];
#pragma unroll
            for (int nf = 0; nf < 8; nf++) {
                const int nr = nf * 8 + g;
                mma_f16(oacc[nf], a0, a1, a2, a3,
                        Vs[nr * VSTR + kb], Vs[nr * VSTR + kb + 4]);
            }
        }
        __syncthreads();
    }

    // ---- epilogue: divide by l, write o[b, q, h*64+d] ----
    const float inv0 = 1.f / l_r[0];
    const float inv1 = 1.f / l_r[1];
#pragma unroll
    for (int nf = 0; nf < 8; nf++) {
        const int row = qt * 64 + wm + g;
        const int col = nf * 8 + 2 * c;
        float* ob = o + (size_t)(b * 512 + row) * 512 + h * 64 + col;
        ob[0]           = oacc[nf][0] * inv0;
        ob[1]           = oacc[nf][1] * inv0;
        ob[8 * 512]     = oacc[nf][2] * inv1;
        ob[8 * 512 + 1] = oacc[nf][3] * inv1;
    }
}

// ---------------------------------------------------------------------------
// Row softmax, row length = CPT*256, one block of 256 threads per row
// ---------------------------------------------------------------------------
template <int CPT>
__global__ void __launch_bounds__(256) softmax_kernel(float* __restrict__ data)
{
    float* row = data + (size_t)blockIdx.x * (CPT * 256);
    const int tid = threadIdx.x;
    float x[CPT];
    float mx = -3.402823466e38f;
#pragma unroll
    for (int c = 0; c < CPT; c++) {
        x[c] = row[tid + 256 * c];
        mx = fmaxf(mx, x[c]);
    }
    __shared__ float sh[8];
#pragma unroll
    for (int o = 16; o; o >>= 1) mx = fmaxf(mx, __shfl_xor_sync(0xffffffffu, mx, o));
    if ((tid & 31) == 0) sh[tid >> 5] = mx;
    __syncthreads();
    mx = sh[0];
#pragma unroll
    for (int w = 1; w < 8; w++) mx = fmaxf(mx, sh[w]);

    float s = 0.f;
#pragma unroll
    for (int c = 0; c < CPT; c++) { x[c] = expf(x[c] - mx); s += x[c]; }
    __syncthreads();
#pragma unroll
    for (int o = 16; o; o >>= 1) s += __shfl_xor_sync(0xffffffffu, s, o);
    if ((tid & 31) == 0) sh[tid >> 5] = s;
    __syncthreads();
    float tot = sh[0];
#pragma unroll
    for (int w = 1; w < 8; w++) tot += sh[w];
    float inv = 1.f / tot;
#pragma unroll
    for (int c = 0; c < CPT; c++) row[tid + 256 * c] = x[c] * inv;
}

// ---------------------------------------------------------------------------
// out = LayerNorm(X + Y) * g + b  (row length 512, one block per row)
// ---------------------------------------------------------------------------
__global__ void __launch_bounds__(256) add_ln_kernel(
    const float* __restrict__ X, const float* __restrict__ Y,
    const float* __restrict__ gam, const float* __restrict__ bet,
    float* __restrict__ out)
{
    const size_t row = blockIdx.x;
    const float* xr = X + row * 512;
    const float* yr = Y + row * 512;
    const int tid = threadIdx.x;
    float t0 = xr[tid] + yr[tid];
    float t1 = xr[tid + 256] + yr[tid + 256];

    __shared__ float sh[8];
    float s = t0 + t1;
#pragma unroll
    for (int o = 16; o; o >>= 1) s += __shfl_xor_sync(0xffffffffu, s, o);
    if ((tid & 31) == 0) sh[tid >> 5] = s;
    __syncthreads();
    float tot = sh[0];
#pragma unroll
    for (int w = 1; w < 8; w++) tot += sh[w];
    float mean = tot * (1.f / 512.f);
    float d0 = t0 - mean, d1 = t1 - mean;
    float q = d0 * d0 + d1 * d1;
    __syncthreads();
#pragma unroll
    for (int o = 16; o; o >>= 1) q += __shfl_xor_sync(0xffffffffu, q, o);
    if ((tid & 31) == 0) sh[tid >> 5] = q;
    __syncthreads();
    float vtot = sh[0];
#pragma unroll
    for (int w = 1; w < 8; w++) vtot += sh[w];
    float inv = rsqrtf(vtot * (1.f / 512.f) + 1e-5f);
    float* orow = out + row * 512;
    orow[tid] = d0 * inv * gam[tid] + bet[tid];
    orow[tid + 256] = d1 * inv * gam[tid + 256] + bet[tid + 256];
}

// ---------------------------------------------------------------------------
// Graph branch (exact fp32, tiny cost)
// ---------------------------------------------------------------------------
__global__ void feat_fn_kernel(const float* __restrict__ x, float* __restrict__ fn)
{
    const int b = blockIdx.x, i = threadIdx.x; // 64 threads
    const float* xp = x + (size_t)b * 32768 + i;
    float s = 0.f;
    for (int t = 0; t < 512; t++) s += xp[(size_t)t * 64];
    float f = s * (1.f / 512.f);
    __shared__ float sh[64];
    sh[i] = f * f;
    __syncthreads();
    for (int o = 32; o; o >>= 1) {
        if (i < o) sh[i] += sh[i + o];
        __syncthreads();
    }
    float norm = sqrtf(sh[0]);
    fn[b * 64 + i] = f / fmaxf(norm, 1e-12f);
}

__global__ void graph_adj_kernel(const float* __restrict__ fn, float* __restrict__ An)
{
    const int b = blockIdx.x, i = threadIdx.x; // 64 threads
    __shared__ float f[64];
    __shared__ unsigned char A[64][64];
    f[i] = fn[b * 64 + i];
    for (int j = 0; j < 64; j++) A[i][j] = 0;
    __syncthreads();
    const float fi = f[i];
    float bv0 = -3.402823466e38f, bv1 = bv0, bv2 = bv0, bv3 = bv0;
    int i0 = 0, i1 = 0, i2 = 0, i3 = 0;
    for (int j = 0; j < 64; j++) {
        float v = fi * f[j];
        if (v > bv3) {
            if (v > bv0)      { bv3 = bv2; i3 = i2; bv2 = bv1; i2 = i1; bv1 = bv0; i1 = i0; bv0 = v; i0 = j; }
            else if (v > bv1) { bv3 = bv2; i3 = i2; bv2 = bv1; i2 = i1; bv1 = v; i1 = j; }
            else if (v > bv2) { bv3 = bv2; i3 = i2; bv2 = v; i2 = j; }
            else              { bv3 = v; i3 = j; }
        }
    }
    A[i][i1] = 1; A[i][i2] = 1; A[i][i3] = 1;
    __syncthreads();
    float deg = 0.f;
    for (int j = 0; j < 64; j++) {
        bool a = (j == i) || A[i][j] || A[j][i];
        deg += a ? 1.f : 0.f;
    }
    float inv = 1.f / deg;
    float* row = An + (size_t)b * 4096 + i * 64;
    for (int j = 0; j < 64; j++) {
        bool a = (j == i) || A[i][j] || A[j][i];
        row[j] = a ? inv : 0.f;
    }
}

// t1[b,f,d] = sum_s x[b,s,f] * w[d,s] + bias[d]   (M=64 f, N=512 d, K=512 s)
__global__ void __launch_bounds__(256) gcn_gemm1_kernel(
    const float* __restrict__ x, const float* __restrict__ w,
    const float* __restrict__ bias, float* __restrict__ out)
{
    const int dt = blockIdx.x, b = blockIdx.y;
    __shared__ float Xs[16][64];
    __shared__ float Ws[64][17];
    const int tid = threadIdx.x, tx = tid & 15, ty = tid >> 4;
    float acc[4][4];
#pragma unroll
    for (int i = 0; i < 4; i++)
#pragma unroll
        for (int j = 0; j < 4; j++) acc[i][j] = 0.f;

    for (int k0 = 0; k0 < 512; k0 += 16) {
        {
            int kk = tid >> 4, f4 = (tid & 15) << 2;
            float4 v = *reinterpret_cast<const float4*>(
                x + (size_t)b * 32768 + (size_t)(k0 + kk) * 64 + f4);
            *reinterpret_cast<float4*>(&Xs[kk][f4]) = v;
            int dd = tid >> 2, k4 = (tid & 3) << 2;
            float4 w4 = *reinterpret_cast<const float4*>(
                w + (size_t)(dt * 64 + dd) * 512 + k0 + k4);
            Ws[dd][k4 + 0] = w4.x; Ws[dd][k4 + 1] = w4.y;
            Ws[dd][k4 + 2] = w4.z; Ws[dd][k4 + 3] = w4.w;
        }
        __syncthreads();
#pragma unroll
        for (int kk = 0; kk < 16; kk++) {
            float a[4], bb[4];
#pragma unroll
            for (int i = 0; i < 4; i++) a[i] = Xs[kk][ty + 16 * i];
#pragma unroll
            for (int j = 0; j < 4; j++) bb[j] = Ws[tx + 16 * j][kk];
#pragma unroll
            for (int i = 0; i < 4; i++)
#pragma unroll
                for (int j = 0; j < 4; j++)
                    acc[i][j] = fmaf(a[i], bb[j], acc[i][j]);
        }
        __syncthreads();
    }
#pragma unroll
    for (int i = 0; i < 4; i++)
#pragma unroll
        for (int j = 0; j < 4; j++) {
            int dd = dt * 64 + tx + 16 * j;
            out[(size_t)b * 32768 + (size_t)(ty + 16 * i) * 512 + dd] =
                acc[i][j] + bias[dd];
        }
}

// t2[b,f,s] = sum_d Ain[b,f,d] * w[s,d] + bias[s]
__global__ void __launch_bounds__(256) gcn_gemm2_kernel(
    const float* __restrict__ Ain, const float* __restrict__ w,
    const float* __restrict__ bias, float* __restrict__ out)
{
    const int st = blockIdx.x, b = blockIdx.y;
    __shared__ float As[64][17];
    __shared__ float Ws[64][17];
    const int tid = threadIdx.x, tx = tid & 15, ty = tid >> 4;
    const int rr = tid >> 2, k4 = (tid & 3) << 2;
    float acc[4][4];
#pragma unroll
    for (int i = 0; i < 4; i++)
#pragma unroll
        for (int j = 0; j < 4; j++) acc[i][j] = 0.f;

    for (int k0 = 0; k0 < 512; k0 += 16) {
        float4 a4 = *reinterpret_cast<const float4*>(
            Ain + (size_t)b * 32768 + (size_t)rr * 512 + k0 + k4);
        As[rr][k4 + 0] = a4.x; As[rr][k4 + 1] = a4.y;
        As[rr][k4 + 2] = a4.z; As[rr][k4 + 3] = a4.w;
        float4 w4 = *reinterpret_cast<const float4*>(
            w + (size_t)(st * 64 + rr) * 512 + k0 + k4);
        Ws[rr][k4 + 0] = w4.x; Ws[rr][k4 + 1] = w4.y;
        Ws[rr][k4 + 2] = w4.z; Ws[rr][k4 + 3] = w4.w;
        __syncthreads();
#pragma unroll
        for (int kk = 0; kk < 16; kk++) {
            float a[4], bb[4];
#pragma unroll
            for (int i = 0; i < 4; i++) a[i] = As[ty + 16 * i][kk];
#pragma unroll
            for (int j = 0; j < 4; j++) bb[j] = Ws[tx + 16 * j][kk];
#pragma unroll
            for (int i = 0; i < 4; i++)
#pragma unroll
                for (int j = 0; j < 4; j++)
                    acc[i][j] = fmaf(a[i], bb[j], acc[i][j]);
        }
        __syncthreads();
    }
#pragma unroll
    for (int i = 0; i < 4; i++)
#pragma unroll
        for (int j = 0; j < 4; j++) {
            int ss = st * 64 + tx + 16 * j;
            out[(size_t)b * 32768 + (size_t)(ty + 16 * i) * 512 + ss] =
                acc[i][j] + bias[ss];
        }
}

// out = (relu?) An @ in ; optional transposed write g_out[b, s, f]
template <bool RELU, bool TRANSOUT>
__global__ void __launch_bounds__(256) an_mult_kernel(
    const float* __restrict__ An, const float* __restrict__ in,
    float* __restrict__ out)
{
    const int dt = blockIdx.x, b = blockIdx.y;
    __shared__ float As[64][65];
    __shared__ float Ins[64][64];
    const int tid = threadIdx.x, tx = tid & 15, ty = tid >> 4;

    for (int t = tid; t < 4096; t += 256)
        As[t >> 6][t & 63] = An[(size_t)b * 4096 + t];
#pragma unroll
    for (int hh = 0; hh < 4; hh++) {
        int idx4 = tid + hh * 256;
        int gg = idx4 >> 4, c4 = (idx4 & 15) << 2;
        float4 v = *reinterpret_cast<const float4*>(
            in + (size_t)b * 32768 + (size_t)gg * 512 + dt * 64 + c4);
        *reinterpret_cast<float4*>(&Ins[gg][c4]) = v;
    }
    __syncthreads();

    float acc[4][4];
#pragma unroll
    for (int i = 0; i < 4; i++)
#pragma unroll
        for (int j = 0; j < 4; j++) acc[i][j] = 0.f;

#pragma unroll 8
    for (int kk = 0; kk < 64; kk++) {
        float a[4], bb[4];
#pragma unroll
        for (int i = 0; i < 4; i++) a[i] = As[ty + 16 * i][kk];
#pragma unroll
        for (int j = 0; j < 4; j++) bb[j] = Ins[kk][tx + 16 * j];
#pragma unroll
        for (int i = 0; i < 4; i++)
#pragma unroll
            for (int j = 0; j < 4; j++)
                acc[i][j] = fmaf(a[i], bb[j], acc[i][j]);
    }

#pragma unroll
    for (int i = 0; i < 4; i++)
#pragma unroll
        for (int j = 0; j < 4; j++) {
            int ff = ty + 16 * i;
            int dd = dt * 64 + tx + 16 * j;
            float v = acc[i][j];
            if (RELU) v = fmaxf(v, 0.f);
            if (!TRANSOUT)
                out[(size_t)b * 32768 + (size_t)ff * 512 + dd] = v;
            else
                out[(size_t)b * 32768 + (size_t)dd * 64 + ff] = v;
        }
}

// ---------------------------------------------------------------------------
// Host orchestration
// ---------------------------------------------------------------------------
extern "C" void kernel_launch(void* const* d_in, const int* in_sizes, int n_in,
                              void* d_out, int out_size)
{
    const float* x      = (const float*)d_in[0];
    const float* W_in   = (const float*)d_in[1];
    const float* b_in   = (const float*)d_in[2];
    const float* qkv_w  = (const float*)d_in[3];
    const float* qkv_b  = (const float*)d_in[4];
    const float* out_w  = (const float*)d_in[5];
    const float* out_b  = (const float*)d_in[6];
    const float* ln1_g  = (const float*)d_in[7];
    const float* ln1_b  = (const float*)d_in[8];
    const float* ln2_g  = (const float*)d_in[9];
    const float* ln2_b  = (const float*)d_in[10];
    const float* ff1_w  = (const float*)d_in[11];
    const float* ff1_b  = (const float*)d_in[12];
    const float* ff2_w  = (const float*)d_in[13];
    const float* ff2_b  = (const float*)d_in[14];
    const float* memory = (const float*)d_in[15];
    const float* fc1_w  = (const float*)d_in[16];
    const float* fc1_b  = (const float*)d_in[17];
    const float* fc2_w  = (const float*)d_in[18];
    const float* fc2_b  = (const float*)d_in[19];
    const float* gc1_w  = (const float*)d_in[20];
    const float* gc1_b  = (const float*)d_in[21];
    const float* gc2_w  = (const float*)d_in[22];
    const float* gc2_b  = (const float*)d_in[23];

    float* out    = (float*)d_out;
    float* t_out  = out;                       // (32,512,64)
    float* gout_p = out + 1048576;             // (32,512,64)
    float* attn_p = out + 2097152;             // (32,512,1024)

    static float *p_pe = nullptr, *p_h, *p_tmp, *p_qkv, *p_o, *p_ff,
                 *p_upd, *p_t1, *p_fn, *p_An, *p_gt1, *p_gh1;
    if (!p_pe) {
        cudaGetSymbolAddress((void**)&p_pe,  g_pe);
        cudaGetSymbolAddress((void**)&p_h,   g_h);
        cudaGetSymbolAddress((void**)&p_tmp, g_tmp);
        cudaGetSymbolAddress((void**)&p_qkv, g_qkv);
        cudaGetSymbolAddress((void**)&p_o,   g_o);
        cudaGetSymbolAddress((void**)&p_ff,  g_ff);
        cudaGetSymbolAddress((void**)&p_upd, g_upd);
        cudaGetSymbolAddress((void**)&p_t1,  g_t1);
        cudaGetSymbolAddress((void**)&p_fn,  g_fn);
        cudaGetSymbolAddress((void**)&p_An,  g_An);
        cudaGetSymbolAddress((void**)&p_gt1, g_gt1);
        cudaGetSymbolAddress((void**)&p_gh1, g_gh1);
    }

    const int M = 16384;

    // positional encoding
    pe_kernel<<<(512 * 512 + 255) / 256, 256>>>(p_pe);

    // h = x @ W_in^T + b_in + pe
    gemm_tc<true, 2, false><<<dim3(4, 128), 256>>>(
        x, nullptr, W_in, b_in, p_pe, p_h, M, 512, 64);

    for (int l = 0; l < 3; l++) {
        // qkv
        gemm_tc<true, 0, false><<<dim3(12, 128), 256>>>(
            p_h, nullptr, qkv_w + (size_t)l * 1536 * 512, qkv_b + l * 1536, nullptr,
            p_qkv, M, 1536, 512);
        // fused attention (scores + softmax + att@v, no materialized scores)
        flash_attn_tc<<<dim3(8, 256), 128>>>(p_qkv, p_o);
        // out projection
        gemm_tc<true, 0, false><<<dim3(4, 128), 256>>>(
            p_o, nullptr, out_w + (size_t)l * 512 * 512, out_b + l * 512, nullptr,
            p_tmp, M, 512, 512);
        add_ln_kernel<<<16384, 256>>>(p_h, p_tmp, ln1_g + l * 512, ln1_b + l * 512, p_h);
        // feed-forward
        gemm_tc<true, 1, false><<<dim3(16, 128), 256>>>(
            p_h, nullptr, ff1_w + (size_t)l * 2048 * 512, ff1_b + l * 2048, nullptr,
            p_ff, M, 2048, 512);
        gemm_tc<true, 0, false><<<dim3(4, 128), 256>>>(
            p_ff, nullptr, ff2_w + (size_t)l * 512 * 2048, ff2_b + l * 512, nullptr,
            p_tmp, M, 512, 2048);
        add_ln_kernel<<<16384, 256>>>(p_h, p_tmp, ln2_g + l * 512, ln2_b + l * 512, p_h);
    }

    // memory attention: sims (split fp16 for accuracy) -> softmax -> upd
    gemm_tc<true, 0, true><<<dim3(8, 128), 256>>>(
        p_h, nullptr, memory, nullptr, nullptr, attn_p, M, 1024, 512);
    softmax_kernel<4><<<16384, 256>>>(attn_p);
    gemm_tc<false, 0, false><<<dim3(4, 128), 256>>>(
        attn_p, nullptr, memory, nullptr, nullptr, p_upd, M, 512, 1024);
    // fc1 over virtual concat [h | upd] (CATAB), then fc2
    gemm_tc<true, 1, false, true><<<dim3(4, 128), 256>>>(
        p_h, p_upd, fc1_w, fc1_b, nullptr, p_t1, M, 512, 1024);
    gemm_tc<true, 0, false><<<dim3(1, 128), 256>>>(
        p_t1, nullptr, fc2_w, fc2_b, nullptr, t_out, M, 64, 512);

    // graph branch (exact fp32)
    feat_fn_kernel<<<32, 64>>>(x, p_fn);
    graph_adj_kernel<<<32, 64>>>(p_fn, p_An);
    gcn_gemm1_kernel<<<dim3(8, 32), 256>>>(x, gc1_w, gc1_b, p_gt1);
    an_mult_kernel<true, false><<<dim3(8, 32), 256>>>(p_An, p_gt1, p_gh1);
    gcn_gemm2_kernel<<<dim3(8, 32), 256>>>(p_gh1, gc2_w, gc2_b, p_gt1);
    an_mult_kernel<false, true><<<dim3(8, 32), 256>>>(p_An, p_gt1, gout_p);

    (void)in_sizes; (void)n_in; (void)out_size;
}